// round 1
// baseline (speedup 1.0000x reference)
#include <cuda_runtime.h>
#include <math.h>

#define NN 8192
#define NE 65536

#define INV_SQRT32  0.17677669529663687f
#define INV_SQRT128 0.08838834764831843f
#define INV_SQRT512 0.04419417382415922f
#define INV_SQRT3   0.5773502691896258f
#define INV_SQRT160 0.07905694150420949f

// ---------------- scratch (device globals; allocation-free contract) ----------
__device__ float g_S[NN * 1600];        // per-node scalar outputs: Q_s|Ak_s|Bk_s|PA_s|PB_s
__device__ float g_V[NN * 2496];        // per-node vector outputs (o*3+c): Q_v|Ak_v|Bk_v|PA_v|PB_v
__device__ float g_QKself[NN * 8];
__device__ float g_c0[NE * 64];
__device__ float g_sv[NE * 96];
__device__ float g_val[83886080];       // NE * 1280
__device__ float g_ex[NE * 8];
__device__ float g_logit[NE * 8];
__device__ float g_nmax[NN * 8];
__device__ float g_nden[NN * 8];
__device__ float g_msg[NN * 1280];
__device__ float g_m[NN * 160];
__device__ int   g_cnt[NN];
__device__ int   g_offs[NN + 1];
__device__ int   g_cursor[NN];
__device__ int   g_elist[NE];
// packed, pre-scaled weights
__device__ float g_Wps[64 * 1600];
__device__ float g_Wpv[32 * 832];
__device__ float g_Wvs[64 * 512];
__device__ float g_Wve[32 * 256];
__device__ float g_Wms[512 * 64];
__device__ float g_Wmv[256 * 32];

// ---------------- helpers -----------------------------------------------------
__device__ __forceinline__ void atomicMaxFloat(float* addr, float val) {
    int* ia = (int*)addr;
    int old = *ia;
    while (__int_as_float(old) < val) {
        int assumed = old;
        old = atomicCAS(ia, assumed, __float_as_int(val));
        if (old == assumed) break;
    }
}

// ---------------- weight packing ----------------------------------------------
__global__ void k_pack(const float* __restrict__ Wq_s, const float* __restrict__ Wq_v,
                       const float* __restrict__ Wk_s, const float* __restrict__ Wk_v,
                       const float* __restrict__ Wp_s, const float* __restrict__ Wp_v,
                       const float* __restrict__ Wv_s, const float* __restrict__ Wv_v,
                       const float* __restrict__ Wm_s, const float* __restrict__ Wm_v) {
    int i = blockIdx.x * 256 + threadIdx.x;
    if (i < 64 * 1600) {
        int k = i / 1600, c = i % 1600; float w;
        if (c < 512)       w = Wq_s[k * 512 + c] * 0.125f;
        else if (c < 1024) w = Wk_s[k * 512 + (c - 512)] * INV_SQRT128;
        else if (c < 1536) w = Wk_s[(64 + k) * 512 + (c - 1024)] * INV_SQRT128;
        else if (c < 1568) w = Wp_s[k * 32 + (c - 1536)] * INV_SQRT128;
        else               w = Wp_s[(64 + k) * 32 + (c - 1568)] * INV_SQRT128;
        g_Wps[i] = w; return;
    }
    i -= 64 * 1600;
    if (i < 32 * 832) {
        int k = i / 832, c = i % 832; float w;
        if (c < 256)      w = Wq_v[k * 256 + c] * INV_SQRT32;
        else if (c < 512) w = Wk_v[k * 256 + (c - 256)] * 0.125f;
        else if (c < 768) w = Wk_v[(32 + k) * 256 + (c - 512)] * 0.125f;
        else if (c < 800) w = Wp_v[k * 32 + (c - 768)] * 0.125f;
        else              w = Wp_v[(32 + k) * 32 + (c - 800)] * 0.125f;
        g_Wpv[i] = w; return;
    }
    i -= 32 * 832;
    if (i < 64 * 512) { g_Wvs[i] = Wv_s[i] * 0.125f; return; }
    i -= 64 * 512;
    if (i < 32 * 256) {
        int k = i / 256, o = i % 256;
        g_Wve[i] = (Wv_v[k * 256 + o] + Wv_v[(32 + k) * 256 + o]) * 0.125f; return;
    }
    i -= 32 * 256;
    if (i < 512 * 64) { g_Wms[i] = Wm_s[i] * INV_SQRT512; return; }
    i -= 512 * 64;
    if (i < 256 * 32) { g_Wmv[i] = Wm_v[i] * 0.0625f; return; }
}

// ---------------- generic tiled fp32 GEMM --------------------------------------
// C[m, ccol0 + col*cCol + comp*cComp] = sum_k A[m*aRow + k*aCol + comp*aComp] * W[k*WO + col]
// BM=64, BN=64, BK=32, 256 threads, 4x4 per thread. M % 64 == 0, K % 32 == 0.
__global__ void __launch_bounds__(256) k_gemm(
    const float* __restrict__ A, int aRow, int aCol, int aComp,
    const float* __restrict__ W, int WO,
    float* __restrict__ C, int cRow, int cCol, int cComp, int ccol0,
    int K, int NC) {
    __shared__ __align__(16) float As[32 * 68];
    __shared__ __align__(16) float Ws[32 * 68];
    int tid = threadIdx.x;
    int m0 = blockIdx.y * 64;
    int n0 = blockIdx.x * 64;
    int comp = blockIdx.z;
    const float* Ab = A + (size_t)comp * aComp;
    float acc[4][4] = {};
    int ty = tid >> 4, tx = tid & 15;

    for (int k0 = 0; k0 < K; k0 += 32) {
#pragma unroll
        for (int r = 0; r < 8; r++) {
            int l = tid + r * 256;
            int kk = l & 31, mm = l >> 5;
            As[kk * 68 + mm] = Ab[(size_t)(m0 + mm) * aRow + (size_t)(k0 + kk) * aCol];
        }
#pragma unroll
        for (int r = 0; r < 8; r++) {
            int l = tid + r * 256;
            int kk = l >> 6, jj = l & 63;
            int col = n0 + jj;
            Ws[kk * 68 + jj] = (col < NC) ? W[(size_t)(k0 + kk) * WO + col] : 0.f;
        }
        __syncthreads();
#pragma unroll
        for (int k = 0; k < 32; k++) {
            float4 a4 = *(const float4*)&As[k * 68 + ty * 4];
            float4 b4 = *(const float4*)&Ws[k * 68 + tx * 4];
            float av[4] = {a4.x, a4.y, a4.z, a4.w};
            float bv[4] = {b4.x, b4.y, b4.z, b4.w};
#pragma unroll
            for (int i = 0; i < 4; i++)
#pragma unroll
                for (int j = 0; j < 4; j++)
                    acc[i][j] += av[i] * bv[j];
        }
        __syncthreads();
    }
#pragma unroll
    for (int i = 0; i < 4; i++) {
        int m = m0 + ty * 4 + i;
#pragma unroll
        for (int j = 0; j < 4; j++) {
            int col = n0 + tx * 4 + j;
            if (col < NC)
                C[(size_t)m * cRow + (size_t)comp * cComp + ccol0 + (size_t)col * cCol] = acc[i][j];
        }
    }
}

// ---------------- per-(node,head) self dot q . A_k ------------------------------
__global__ void __launch_bounds__(256) k_qkself() {
    int wid = blockIdx.x * 8 + (threadIdx.x >> 5);
    int lane = threadIdx.x & 31;
    int n = wid >> 3, h = wid & 7;
    const float* S = g_S + n * 1600;
    const float* V = g_V + n * 2496;
    float a = 0.f;
    a += S[h * 64 + lane]      * S[512 + h * 64 + lane];
    a += S[h * 64 + 32 + lane] * S[512 + h * 64 + 32 + lane];
#pragma unroll
    for (int t = 0; t < 3; t++) {
        int j = lane + t * 32;
        a += V[h * 96 + j] * V[768 + h * 96 + j];
    }
#pragma unroll
    for (int o = 16; o; o >>= 1) a += __shfl_xor_sync(0xffffffffu, a, o);
    if (lane == 0) g_QKself[n * 8 + h] = a;
}

// ---------------- init ----------------------------------------------------------
__global__ void k_init() {
    int i = blockIdx.x * 256 + threadIdx.x;
    if (i < NN * 8) { g_nmax[i] = -3.402823466e38f; g_nden[i] = 0.f; }
    if (i < NN) g_cnt[i] = 0;
}

// ---------------- CSR build ------------------------------------------------------
__global__ void k_hist(const int* __restrict__ ei) {
    int e = blockIdx.x * 256 + threadIdx.x;
    if (e < NE) atomicAdd(&g_cnt[ei[NE + e]], 1);
}

__global__ void __launch_bounds__(1024) k_scan() {
    __shared__ int wsum[32];
    int tid = threadIdx.x;
    int base = tid * 8;
    int loc[8]; int tot = 0;
#pragma unroll
    for (int i = 0; i < 8; i++) { loc[i] = tot; tot += g_cnt[base + i]; }
    int lane = tid & 31, w = tid >> 5;
    int incl = tot;
#pragma unroll
    for (int o = 1; o < 32; o <<= 1) {
        int y = __shfl_up_sync(0xffffffffu, incl, o);
        if (lane >= o) incl += y;
    }
    if (lane == 31) wsum[w] = incl;
    int excl = incl - tot;
    __syncthreads();
    if (w == 0) {
        int t = wsum[lane];
        int i2 = t;
#pragma unroll
        for (int o = 1; o < 32; o <<= 1) {
            int y = __shfl_up_sync(0xffffffffu, i2, o);
            if (lane >= o) i2 += y;
        }
        wsum[lane] = i2 - t;
    }
    __syncthreads();
    int off = wsum[w] + excl;
#pragma unroll
    for (int i = 0; i < 8; i++) {
        int o2 = off + loc[i];
        g_offs[base + i] = o2;
        g_cursor[base + i] = o2;
    }
    if (tid == 1023) g_offs[NN] = NE;
}

__global__ void k_scatter(const int* __restrict__ ei) {
    int e = blockIdx.x * 256 + threadIdx.x;
    if (e < NE) {
        int pos = atomicAdd(&g_cursor[ei[NE + e]], 1);
        g_elist[pos] = e;
    }
}

// ---------------- per-edge sph / c0 / sv ------------------------------------------
__global__ void __launch_bounds__(256) k_edgeprep(const float* __restrict__ rbf,
                                                  const float* __restrict__ rsh,
                                                  const int* __restrict__ ei,
                                                  const float* __restrict__ Wrbf) {
    __shared__ float sW[1024];
    int tid = threadIdx.x;
    for (int l = tid; l < 1024; l += 256) sW[l] = Wrbf[l];
    __syncthreads();
    int e = blockIdx.x * 8 + (tid >> 5);
    int lane = tid & 31;
    int src = ei[e], dst = ei[NE + e];
    int d = lane;
    float ps  = g_S[src * 1600 + 1536 + d] + g_S[dst * 1600 + 1568 + d];
    float pv0 = g_V[src * 2496 + 2304 + d * 3 + 0] + g_V[dst * 2496 + 2400 + d * 3 + 0];
    float pv1 = g_V[src * 2496 + 2304 + d * 3 + 1] + g_V[dst * 2496 + 2400 + d * 3 + 1];
    float pv2 = g_V[src * 2496 + 2304 + d * 3 + 2] + g_V[dst * 2496 + 2400 + d * 3 + 2];
    float rval = (lane < 16) ? rbf[e * 16 + lane] : 0.f;
    float scal_s = 0.f, scal_v = 0.f;
#pragma unroll
    for (int b = 0; b < 16; b++) {
        float rb = __shfl_sync(0xffffffffu, rval, b);
        scal_s += rb * sW[b * 64 + d];
        scal_v += rb * sW[b * 64 + 32 + d];
    }
    float rs  = rsh[e * 128 + d];
    float rv0 = rsh[e * 128 + 32 + d * 3 + 0];
    float rv1 = rsh[e * 128 + 32 + d * 3 + 1];
    float rv2 = rsh[e * 128 + 32 + d * 3 + 2];
    float sph_s = rs * scal_s * ps;
    float sv0 = rv0 * scal_v * pv0;
    float sv1 = rv1 * scal_v * pv1;
    float sv2 = rv2 * scal_v * pv2;
    g_c0[e * 64 + d]      = sph_s * sph_s;
    g_c0[e * 64 + 32 + d] = (sv0 * sv0 + sv1 * sv1 + sv2 * sv2) * INV_SQRT3;
    g_sv[e * 96 + d * 3 + 0] = sph_s * sv0;
    g_sv[e * 96 + d * 3 + 1] = sph_s * sv1;
    g_sv[e * 96 + d * 3 + 2] = sph_s * sv2;
}

// ---------------- logits + scatter max ---------------------------------------------
__global__ void __launch_bounds__(256) k_logits(const int* __restrict__ ei) {
    int e = blockIdx.x * 8 + (threadIdx.x >> 5);
    int lane = threadIdx.x & 31;
    int src = ei[e], dst = ei[NE + e];
    const float* Qs = g_S + src * 1600;
    const float* Bs = g_S + dst * 1600 + 1024;
    const float* Qv = g_V + src * 2496;
    const float* Bv = g_V + dst * 2496 + 1536;
    float my = 0.f;
#pragma unroll
    for (int h = 0; h < 8; h++) {
        float a = Qs[h * 64 + lane] * Bs[h * 64 + lane]
                + Qs[h * 64 + 32 + lane] * Bs[h * 64 + 32 + lane];
#pragma unroll
        for (int t = 0; t < 3; t++) {
            int j = h * 96 + lane + t * 32;
            a += Qv[j] * Bv[j];
        }
#pragma unroll
        for (int o = 16; o; o >>= 1) a += __shfl_xor_sync(0xffffffffu, a, o);
        if (lane == h) my = a;
    }
    if (lane < 8) {
        float lg = (my + g_QKself[src * 8 + lane]) * INV_SQRT160;
        g_logit[e * 8 + lane] = lg;
        atomicMaxFloat(&g_nmax[dst * 8 + lane], lg);
    }
}

// ---------------- exp + scatter denominator ----------------------------------------
__global__ void k_expsum(const int* __restrict__ ei) {
    int i = blockIdx.x * 256 + threadIdx.x;
    if (i < NE * 8) {
        int e = i >> 3, h = i & 7;
        int dst = ei[NE + e];
        float ex = expf(g_logit[i] - g_nmax[dst * 8 + h]);
        g_ex[i] = ex;
        atomicAdd(&g_nden[dst * 8 + h], ex);
    }
}

// ---------------- CSR aggregation ---------------------------------------------------
__global__ void __launch_bounds__(256) k_agg() {
    int n = blockIdx.x;
    int tid = threadIdx.x;
    __shared__ float s_inv[8];
    __shared__ float s_attn[64 * 8];
    __shared__ int s_e[64];
    if (tid < 8) {
        float dnm = g_nden[n * 8 + tid];
        s_inv[tid] = (dnm > 0.f) ? 1.f / dnm : 0.f;
    }
    __syncthreads();
    float acc[5] = {0, 0, 0, 0, 0};
    int elem[5], hd[5];
#pragma unroll
    for (int i = 0; i < 5; i++) {
        int el = tid + i * 256;
        elem[i] = el;
        hd[i] = (el < 512) ? (el >> 6) : ((el - 512) / 96);
    }
    int s0 = g_offs[n], s1 = g_offs[n + 1];
    for (int cs = s0; cs < s1; cs += 64) {
        int nc = min(64, s1 - cs);
        __syncthreads();
        for (int l = tid; l < nc * 8; l += 256) {
            int j = l >> 3, h = l & 7;
            int e = g_elist[cs + j];
            if (h == 0) s_e[j] = e;
            s_attn[l] = g_ex[e * 8 + h] * s_inv[h];
        }
        __syncthreads();
        for (int j = 0; j < nc; j++) {
            int e = s_e[j];
            const float* vr = g_val + (size_t)e * 1280;
#pragma unroll
            for (int i = 0; i < 5; i++)
                acc[i] += s_attn[j * 8 + hd[i]] * vr[elem[i]];
        }
    }
#pragma unroll
    for (int i = 0; i < 5; i++) g_msg[n * 1280 + elem[i]] = acc[i];
}

// ---------------- NormGate (EvNorm + MLP gate) + output ------------------------------
__global__ void __launch_bounds__(256) k_normgate(const float* __restrict__ ln_g,
                                                  const float* __restrict__ ln_b,
                                                  const float* __restrict__ W1,
                                                  const float* __restrict__ b1,
                                                  const float* __restrict__ W2,
                                                  const float* __restrict__ b2,
                                                  float* __restrict__ out) {
    __shared__ float sX[8][96];
    __shared__ float sH[8][96];
    int w = threadIdx.x >> 5, lane = threadIdx.x & 31;
    int n = blockIdx.x * 8 + w;
    const float* mrow = g_m + n * 160;
    float ms0 = mrow[lane], ms1 = mrow[32 + lane];
    float v0 = mrow[64 + lane * 3 + 0];
    float v1 = mrow[64 + lane * 3 + 1];
    float v2 = mrow[64 + lane * 3 + 2];
    float n00 = fabsf(ms0), n01 = fabsf(ms1);
    float n02 = sqrtf(v0 * v0 + v1 * v1 + v2 * v2);
    float s = n00 + n01 + n02;
    float s2 = n00 * n00 + n01 * n01 + n02 * n02;
#pragma unroll
    for (int o = 16; o; o >>= 1) {
        s  += __shfl_xor_sync(0xffffffffu, s, o);
        s2 += __shfl_xor_sync(0xffffffffu, s2, o);
    }
    float mu = s * (1.f / 96.f);
    float var = s2 * (1.f / 96.f) - mu * mu;
    float rstd = rsqrtf(var + 1e-5f);
    sX[w][lane]      = (n00 - mu) * rstd * ln_g[lane]      + ln_b[lane];
    sX[w][lane + 32] = (n01 - mu) * rstd * ln_g[lane + 32] + ln_b[lane + 32];
    sX[w][lane + 64] = (n02 - mu) * rstd * ln_g[lane + 64] + ln_b[lane + 64];
    __syncwarp();
#pragma unroll
    for (int t = 0; t < 3; t++) {
        int jp = lane + t * 32;
        float hs = b1[jp];
        for (int j = 0; j < 96; j++) hs += sX[w][j] * W1[j * 96 + jp];
        sH[w][jp] = hs / (1.f + expf(-hs));
    }
    __syncwarp();
    float n0arr[3] = {n00, n01, n02};
    float f[3];
#pragma unroll
    for (int t = 0; t < 3; t++) {
        int jp = lane + t * 32;
        float gs = b2[jp];
        for (int j = 0; j < 96; j++) gs += sH[w][j] * W2[j * 96 + jp];
        float gg = gs / (1.f + expf(-gs));
        f[t] = gg / (n0arr[t] + 1e-6f);
    }
    out[n * 160 + lane]      = ms0 * f[0];
    out[n * 160 + 32 + lane] = ms1 * f[1];
    out[n * 160 + 64 + lane * 3 + 0] = v0 * f[2];
    out[n * 160 + 64 + lane * 3 + 1] = v1 * f[2];
    out[n * 160 + 64 + lane * 3 + 2] = v2 * f[2];
}

// ---------------- launch ----------------------------------------------------------------
extern "C" void kernel_launch(void* const* d_in, const int* in_sizes, int n_in,
                              void* d_out, int out_size) {
    const float* pseduo_x = (const float*)d_in[0];
    const float* rbf   = (const float*)d_in[1];
    const float* rsh   = (const float*)d_in[2];
    const int*   ei    = (const int*)d_in[3];
    const float* Wq_s  = (const float*)d_in[4];
    const float* Wq_v  = (const float*)d_in[5];
    const float* Wk_s  = (const float*)d_in[6];
    const float* Wk_v  = (const float*)d_in[7];
    const float* Wp_s  = (const float*)d_in[8];
    const float* Wp_v  = (const float*)d_in[9];
    const float* Wrbf  = (const float*)d_in[10];
    const float* Wv_s  = (const float*)d_in[11];
    const float* Wv_v  = (const float*)d_in[12];
    const float* Wm_s  = (const float*)d_in[13];
    const float* Wm_v  = (const float*)d_in[14];
    const float* ln_g  = (const float*)d_in[15];
    const float* ln_b  = (const float*)d_in[16];
    const float* W1    = (const float*)d_in[17];
    const float* b1    = (const float*)d_in[18];
    const float* W2    = (const float*)d_in[19];
    const float* b2    = (const float*)d_in[20];
    float* out = (float*)d_out;

    void* p;
    cudaGetSymbolAddress(&p, g_S);    float* S   = (float*)p;
    cudaGetSymbolAddress(&p, g_V);    float* V   = (float*)p;
    cudaGetSymbolAddress(&p, g_c0);   float* C0  = (float*)p;
    cudaGetSymbolAddress(&p, g_sv);   float* SV  = (float*)p;
    cudaGetSymbolAddress(&p, g_val);  float* VAL = (float*)p;
    cudaGetSymbolAddress(&p, g_msg);  float* MSG = (float*)p;
    cudaGetSymbolAddress(&p, g_m);    float* M   = (float*)p;
    cudaGetSymbolAddress(&p, g_Wps);  float* Wps = (float*)p;
    cudaGetSymbolAddress(&p, g_Wpv);  float* Wpv = (float*)p;
    cudaGetSymbolAddress(&p, g_Wvs);  float* Wvs = (float*)p;
    cudaGetSymbolAddress(&p, g_Wve);  float* Wve = (float*)p;
    cudaGetSymbolAddress(&p, g_Wms);  float* Wms = (float*)p;
    cudaGetSymbolAddress(&p, g_Wmv);  float* Wmv = (float*)p;

    k_init<<<256, 256>>>();
    k_pack<<<824, 256>>>(Wq_s, Wq_v, Wk_s, Wk_v, Wp_s, Wp_v, Wv_s, Wv_v, Wm_s, Wm_v);

    // per-node scalar projections: [8192,64] @ [64,1600]
    k_gemm<<<dim3(25, 128, 1), 256>>>(pseduo_x, 160, 1, 0, Wps, 1600,
                                      S, 1600, 1, 0, 0, 64, 1600);
    // per-node vector projections: 3 x [8192,32] @ [32,832]
    k_gemm<<<dim3(13, 128, 3), 256>>>(pseduo_x + 64, 160, 3, 1, Wpv, 832,
                                      V, 2496, 3, 1, 0, 32, 832);
    k_qkself<<<8192, 256>>>();

    // CSR over dst
    k_hist<<<256, 256>>>(ei);
    k_scan<<<1, 1024>>>();
    k_scatter<<<256, 256>>>(ei);

    // per-edge sph -> c0 / sv
    k_edgeprep<<<8192, 256>>>(rbf, rsh, ei, Wrbf);

    // attention
    k_logits<<<8192, 256>>>(ei);
    k_expsum<<<2048, 256>>>(ei);

    // per-edge value GEMMs
    k_gemm<<<dim3(8, 1024, 1), 256>>>(C0, 64, 1, 0, Wvs, 512,
                                      VAL, 1280, 1, 0, 0, 64, 512);
    k_gemm<<<dim3(4, 1024, 3), 256>>>(SV, 96, 3, 1, Wve, 256,
                                      VAL, 1280, 3, 1, 512, 32, 256);

    // aggregate messages
    k_agg<<<8192, 256>>>();

    // message projection
    k_gemm<<<dim3(1, 128, 1), 256>>>(MSG, 1280, 1, 0, Wms, 64,
                                     M, 160, 1, 0, 0, 512, 64);
    k_gemm<<<dim3(1, 128, 3), 256>>>(MSG + 512, 1280, 3, 1, Wmv, 32,
                                     M, 160, 3, 1, 64, 256, 32);

    // norm-gate + output
    k_normgate<<<1024, 256>>>(ln_g, ln_b, W1, b1, W2, b2, out);
}

// round 2
// speedup vs baseline: 2.4306x; 2.4306x over previous
#include <cuda_runtime.h>
#include <math.h>
#include <float.h>

#define NN 8192
#define NE 65536

#define INV_SQRT128 0.08838834764831843f
#define INV_SQRT512 0.04419417382415922f
#define INV_SQRT3   0.5773502691896258f
#define INV_SQRT160 0.07905694150420949f
#define INV_SQRT32  0.17677669529663687f

// scale constants (fold fan-in norms + 1/sqrt(msg_dim) into packed weights)
#define SC_S   (0.125f * INV_SQRT128 * INV_SQRT160)   // Wq_s x Wk_s gram
#define SC_V   (INV_SQRT32 * 0.125f * INV_SQRT160)    // Wq_v x Wk_v gram
#define SC_P_S (INV_SQRT128)
#define SC_P_V (0.125f)
#define SC_C_S (0.125f * INV_SQRT512)                 // Wv_s x Wm_s
#define SC_C_V (0.125f * 0.0625f)                     // Wv_v(fold) x Wm_v

// ---------------- scratch ------------------------------------------------------
__device__ float g_S[NN * 1088];      // per node: tk_s(512) | tself_s(512) | PA_s(32) | PB_s(32)
__device__ float g_V[NN * 1728];      // per node, (col*3+comp): tk_v(256) | tself_v(256) | PAv(32) | PBv(32)
__device__ float g_QKself[NN * 8];
__device__ float g_feat[NE * 160];    // per edge: c0(64) | sv(96)
__device__ float g_logit[NE * 8];     // CSR-slot indexed; logits then ex in-place
__device__ float g_agg[NN * 1280];    // per node: agg_s(512 h-major) | agg_v(768: c*256+h*32+k)
__device__ float g_m[NN * 160];
__device__ int   g_cnt[NN];
__device__ int   g_offs[NN + 1];
__device__ int   g_cursor[NN];
__device__ int   g_elist[NE];
// packed weights
__device__ float g_Wts[64 * 1088];
__device__ float g_Wtv[32 * 576];
__device__ float g_Wcs[512 * 64];
__device__ float g_Wcv[256 * 32];

// ---------------- weight packing / gram precompute -----------------------------
__global__ void k_pack(const float* __restrict__ Wq_s, const float* __restrict__ Wq_v,
                       const float* __restrict__ Wk_s, const float* __restrict__ Wk_v,
                       const float* __restrict__ Wp_s, const float* __restrict__ Wp_v,
                       const float* __restrict__ Wv_s, const float* __restrict__ Wv_v,
                       const float* __restrict__ Wm_s, const float* __restrict__ Wm_v) {
    int i = blockIdx.x * 256 + threadIdx.x;
    if (i < 64 * 1088) {
        int b = i / 1088, col = i % 1088;
        float w = 0.f;
        if (col < 512) {                       // cross gram: Ms_h[a,b] = sum_j Wq[a,hj]*Wk[64+b,hj]
            int h = col >> 6, a = col & 63;
            for (int j = 0; j < 64; j++)
                w += Wq_s[a * 512 + h * 64 + j] * Wk_s[(64 + b) * 512 + h * 64 + j];
            w *= SC_S;
        } else if (col < 1024) {               // self gram
            int c2 = col - 512; int h = c2 >> 6, a = c2 & 63;
            for (int j = 0; j < 64; j++)
                w += Wq_s[a * 512 + h * 64 + j] * Wk_s[b * 512 + h * 64 + j];
            w *= SC_S;
        } else if (col < 1056) {
            w = Wp_s[b * 32 + (col - 1024)] * SC_P_S;
        } else {
            w = Wp_s[(64 + b) * 32 + (col - 1056)] * SC_P_S;
        }
        g_Wts[i] = w; return;
    }
    i -= 64 * 1088;
    if (i < 32 * 576) {
        int b = i / 576, col = i % 576;
        float w = 0.f;
        if (col < 256) {
            int h = col >> 5, a = col & 31;
            for (int j = 0; j < 32; j++)
                w += Wq_v[a * 256 + h * 32 + j] * Wk_v[(32 + b) * 256 + h * 32 + j];
            w *= SC_V;
        } else if (col < 512) {
            int c2 = col - 256; int h = c2 >> 5, a = c2 & 31;
            for (int j = 0; j < 32; j++)
                w += Wq_v[a * 256 + h * 32 + j] * Wk_v[b * 256 + h * 32 + j];
            w *= SC_V;
        } else if (col < 544) {
            w = Wp_v[b * 32 + (col - 512)] * SC_P_V;
        } else {
            w = Wp_v[(32 + b) * 32 + (col - 544)] * SC_P_V;
        }
        g_Wtv[i] = w; return;
    }
    i -= 32 * 576;
    if (i < 512 * 64) {
        int row = i / 64, d = i % 64;
        int h = row >> 6, k = row & 63;
        float w = 0.f;
        for (int j = 0; j < 64; j++)
            w += Wv_s[k * 512 + h * 64 + j] * Wm_s[(h * 64 + j) * 64 + d];
        g_Wcs[i] = w * SC_C_S; return;
    }
    i -= 512 * 64;
    if (i < 256 * 32) {
        int row = i / 32, d = i % 32;
        int h = row >> 5, k = row & 31;
        float w = 0.f;
        for (int j = 0; j < 32; j++)
            w += (Wv_v[k * 256 + h * 32 + j] + Wv_v[(32 + k) * 256 + h * 32 + j])
                 * Wm_v[(h * 32 + j) * 32 + d];
        g_Wcv[i] = w * SC_C_V; return;
    }
}

// ---------------- generic tiled fp32 GEMM ---------------------------------------
__global__ void __launch_bounds__(256) k_gemm(
    const float* __restrict__ A, int aRow, int aCol, int aComp,
    const float* __restrict__ W, int WO,
    float* __restrict__ C, int cRow, int cCol, int cComp, int ccol0,
    int K, int NC) {
    __shared__ __align__(16) float As[32 * 68];
    __shared__ __align__(16) float Ws[32 * 68];
    int tid = threadIdx.x;
    int m0 = blockIdx.y * 64;
    int n0 = blockIdx.x * 64;
    int comp = blockIdx.z;
    const float* Ab = A + (size_t)comp * aComp;
    float acc[4][4] = {};
    int ty = tid >> 4, tx = tid & 15;

    for (int k0 = 0; k0 < K; k0 += 32) {
#pragma unroll
        for (int r = 0; r < 8; r++) {
            int l = tid + r * 256;
            int kk = l & 31, mm = l >> 5;
            As[kk * 68 + mm] = Ab[(size_t)(m0 + mm) * aRow + (size_t)(k0 + kk) * aCol];
        }
#pragma unroll
        for (int r = 0; r < 8; r++) {
            int l = tid + r * 256;
            int kk = l >> 6, jj = l & 63;
            int col = n0 + jj;
            Ws[kk * 68 + jj] = (col < NC) ? W[(size_t)(k0 + kk) * WO + col] : 0.f;
        }
        __syncthreads();
#pragma unroll
        for (int k = 0; k < 32; k++) {
            float4 a4 = *(const float4*)&As[k * 68 + ty * 4];
            float4 b4 = *(const float4*)&Ws[k * 68 + tx * 4];
            float av[4] = {a4.x, a4.y, a4.z, a4.w};
            float bv[4] = {b4.x, b4.y, b4.z, b4.w};
#pragma unroll
            for (int i = 0; i < 4; i++)
#pragma unroll
                for (int j = 0; j < 4; j++)
                    acc[i][j] += av[i] * bv[j];
        }
        __syncthreads();
    }
#pragma unroll
    for (int i = 0; i < 4; i++) {
        int m = m0 + ty * 4 + i;
#pragma unroll
        for (int j = 0; j < 4; j++) {
            int col = n0 + tx * 4 + j;
            if (col < NC)
                C[(size_t)m * cRow + (size_t)comp * cComp + ccol0 + (size_t)col * cCol] = acc[i][j];
        }
    }
}

// ---------------- per-(node,head) self term tself . x ----------------------------
__global__ void __launch_bounds__(256) k_qkself(const float* __restrict__ x) {
    int wid = blockIdx.x * 8 + (threadIdx.x >> 5);
    int lane = threadIdx.x & 31;
    int n = wid >> 3, h = wid & 7;
    const float* ts = g_S + n * 1088 + 512 + h * 64;
    const float* tv = g_V + n * 1728 + 768 + h * 96;
    const float* xr = x + n * 160;
    float a = ts[lane] * xr[lane] + ts[32 + lane] * xr[32 + lane];
#pragma unroll
    for (int t = 0; t < 3; t++) {
        int j = lane + t * 32;
        a += tv[j] * xr[64 + j];
    }
#pragma unroll
    for (int o = 16; o; o >>= 1) a += __shfl_xor_sync(0xffffffffu, a, o);
    if (lane == 0) g_QKself[n * 8 + h] = a;
}

// ---------------- init / CSR ------------------------------------------------------
__global__ void k_init() {
    int i = blockIdx.x * 256 + threadIdx.x;
    if (i < NN) g_cnt[i] = 0;
}

__global__ void k_hist(const int* __restrict__ ei) {
    int e = blockIdx.x * 256 + threadIdx.x;
    if (e < NE) atomicAdd(&g_cnt[ei[NE + e]], 1);
}

__global__ void __launch_bounds__(1024) k_scan() {
    __shared__ int wsum[32];
    int tid = threadIdx.x;
    int base = tid * 8;
    int loc[8]; int tot = 0;
#pragma unroll
    for (int i = 0; i < 8; i++) { loc[i] = tot; tot += g_cnt[base + i]; }
    int lane = tid & 31, w = tid >> 5;
    int incl = tot;
#pragma unroll
    for (int o = 1; o < 32; o <<= 1) {
        int y = __shfl_up_sync(0xffffffffu, incl, o);
        if (lane >= o) incl += y;
    }
    if (lane == 31) wsum[w] = incl;
    int excl = incl - tot;
    __syncthreads();
    if (w == 0) {
        int t = wsum[lane];
        int i2 = t;
#pragma unroll
        for (int o = 1; o < 32; o <<= 1) {
            int y = __shfl_up_sync(0xffffffffu, i2, o);
            if (lane >= o) i2 += y;
        }
        wsum[lane] = i2 - t;
    }
    __syncthreads();
    int off = wsum[w] + excl;
#pragma unroll
    for (int i = 0; i < 8; i++) {
        int o2 = off + loc[i];
        g_offs[base + i] = o2;
        g_cursor[base + i] = o2;
    }
    if (tid == 1023) g_offs[NN] = NE;
}

__global__ void k_scatter(const int* __restrict__ ei) {
    int e = blockIdx.x * 256 + threadIdx.x;
    if (e < NE) {
        int pos = atomicAdd(&g_cursor[ei[NE + e]], 1);
        g_elist[pos] = e;
    }
}

// ---------------- per-edge sph -> feat (c0 | sv) ------------------------------------
__global__ void __launch_bounds__(256) k_edgeprep(const float* __restrict__ rbf,
                                                  const float* __restrict__ rsh,
                                                  const int* __restrict__ ei,
                                                  const float* __restrict__ Wrbf) {
    __shared__ float sW[1024];
    int tid = threadIdx.x;
    for (int l = tid; l < 1024; l += 256) sW[l] = Wrbf[l];
    __syncthreads();
    int e = blockIdx.x * 8 + (tid >> 5);
    int lane = tid & 31;
    int src = ei[e], dst = ei[NE + e];
    int d = lane;
    float ps  = g_S[src * 1088 + 1024 + d] + g_S[dst * 1088 + 1056 + d];
    float pv0 = g_V[src * 1728 + 1536 + d * 3 + 0] + g_V[dst * 1728 + 1632 + d * 3 + 0];
    float pv1 = g_V[src * 1728 + 1536 + d * 3 + 1] + g_V[dst * 1728 + 1632 + d * 3 + 1];
    float pv2 = g_V[src * 1728 + 1536 + d * 3 + 2] + g_V[dst * 1728 + 1632 + d * 3 + 2];
    float rval = (lane < 16) ? rbf[e * 16 + lane] : 0.f;
    float scal_s = 0.f, scal_v = 0.f;
#pragma unroll
    for (int b = 0; b < 16; b++) {
        float rb = __shfl_sync(0xffffffffu, rval, b);
        scal_s += rb * sW[b * 64 + d];
        scal_v += rb * sW[b * 64 + 32 + d];
    }
    float rs  = rsh[e * 128 + d];
    float rv0 = rsh[e * 128 + 32 + d * 3 + 0];
    float rv1 = rsh[e * 128 + 32 + d * 3 + 1];
    float rv2 = rsh[e * 128 + 32 + d * 3 + 2];
    float sph_s = rs * scal_s * ps;
    float sv0 = rv0 * scal_v * pv0;
    float sv1 = rv1 * scal_v * pv1;
    float sv2 = rv2 * scal_v * pv2;
    float* f = g_feat + (size_t)e * 160;
    f[d]      = sph_s * sph_s;
    f[32 + d] = (sv0 * sv0 + sv1 * sv1 + sv2 * sv2) * INV_SQRT3;
    f[64 + d * 3 + 0] = sph_s * sv0;
    f[64 + d * 3 + 1] = sph_s * sv1;
    f[64 + d * 3 + 2] = sph_s * sv2;
}

// ---------------- fused logits + softmax + aggregation (per dst node) ----------------
__global__ void __launch_bounds__(256) k_attn_agg(const float* __restrict__ x,
                                                  const int* __restrict__ ei) {
    int n = blockIdx.x;
    int tid = threadIdx.x;
    int wid = tid >> 5, lane = tid & 31;
    int h = lane >> 2, p = lane & 3;

    __shared__ float s_tk[1280];     // [h*64+a] scalar, 512 + [h*96+j] vec
    __shared__ float s_wmax[8 * 8];
    __shared__ float s_max[8], s_den[8], s_inv[8];
    __shared__ float s_feat[32 * 160];
    __shared__ float s_attn[32 * 8];
    __shared__ int   s_e[32];

    // load tk[dst=n]
    for (int i = tid; i < 512; i += 256) s_tk[i] = g_S[n * 1088 + i];
    for (int i = tid; i < 768; i += 256) s_tk[512 + i] = g_V[n * 1728 + i];
    if (tid < 8) s_den[tid] = 0.f;
    __syncthreads();

    int s0 = g_offs[n], s1 = g_offs[n + 1];
    int deg = s1 - s0;

    // pass 1: logits + warp-local per-head max
    float mymax = -FLT_MAX;
    for (int idx = wid; idx < deg; idx += 8) {
        int e = g_elist[s0 + idx];
        int src = ei[e];
        const float* xs = x + (size_t)src * 160;
        float a = 0.f;
#pragma unroll
        for (int tt = 0; tt < 40; tt++) {
            int t = p * 40 + tt;
            int f = (t < 64) ? (h * 64 + t) : (512 + h * 96 + (t - 64));
            a += s_tk[f] * __ldg(xs + t);
        }
        a += __shfl_xor_sync(0xffffffffu, a, 1);
        a += __shfl_xor_sync(0xffffffffu, a, 2);
        if (p == 0) {
            a += g_QKself[src * 8 + h];
            g_logit[(size_t)(s0 + idx) * 8 + h] = a;
            mymax = fmaxf(mymax, a);
        }
    }
    if (p == 0) s_wmax[wid * 8 + h] = mymax;
    __syncthreads();
    if (tid < 8) {
        float m = -FLT_MAX;
#pragma unroll
        for (int w = 0; w < 8; w++) m = fmaxf(m, s_wmax[w * 8 + tid]);
        s_max[tid] = m;
    }
    __syncthreads();

    // exp + denominator
    for (int i = tid; i < deg * 8; i += 256) {
        int slot = i >> 3, hh = i & 7;
        float ex = expf(g_logit[(size_t)(s0 + slot) * 8 + hh] - s_max[hh]);
        g_logit[(size_t)(s0 + slot) * 8 + hh] = ex;
        atomicAdd(&s_den[hh], ex);
    }
    __syncthreads();
    if (tid < 8) {
        float dnm = s_den[tid];
        s_inv[tid] = (dnm > 0.f) ? 1.f / dnm : 0.f;
    }
    __syncthreads();

    // element mapping for accumulation
    float acc[5] = {0, 0, 0, 0, 0};
    int fidx[5], hd[5], el[5];
#pragma unroll
    for (int i = 0; i < 5; i++) {
        int e2 = tid + i * 256;
        el[i] = e2;
        if (e2 < 512) { hd[i] = e2 >> 6; fidx[i] = e2 & 63; }
        else {
            int r = e2 - 512;
            int k = r & 31, hh = (r >> 5) & 7, c = r >> 8;
            hd[i] = hh; fidx[i] = 64 + k * 3 + c;
        }
    }

    // pass 2: chunks of 32 edges
    for (int cs = 0; cs < deg; cs += 32) {
        int nc = min(32, deg - cs);
        __syncthreads();
        if (tid < nc) s_e[tid] = g_elist[s0 + cs + tid];
        for (int i = tid; i < nc * 8; i += 256) {
            int j = i >> 3, hh = i & 7;
            s_attn[i] = g_logit[(size_t)(s0 + cs + j) * 8 + hh] * s_inv[hh];
        }
        __syncthreads();
        for (int q = tid; q < nc * 40; q += 256) {
            int j = q / 40, w4 = q % 40;
            ((float4*)s_feat)[j * 40 + w4] =
                ((const float4*)(g_feat + (size_t)s_e[j] * 160))[w4];
        }
        __syncthreads();
        for (int j = 0; j < nc; j++) {
            const float* fr = s_feat + j * 160;
            const float* ar = s_attn + j * 8;
#pragma unroll
            for (int i = 0; i < 5; i++)
                acc[i] += ar[hd[i]] * fr[fidx[i]];
        }
    }
#pragma unroll
    for (int i = 0; i < 5; i++) g_agg[(size_t)n * 1280 + el[i]] = acc[i];
}

// ---------------- NormGate + output ---------------------------------------------------
__global__ void __launch_bounds__(256) k_normgate(const float* __restrict__ ln_g,
                                                  const float* __restrict__ ln_b,
                                                  const float* __restrict__ W1,
                                                  const float* __restrict__ b1,
                                                  const float* __restrict__ W2,
                                                  const float* __restrict__ b2,
                                                  float* __restrict__ out) {
    __shared__ float sX[8][96];
    __shared__ float sH[8][96];
    int w = threadIdx.x >> 5, lane = threadIdx.x & 31;
    int n = blockIdx.x * 8 + w;
    const float* mrow = g_m + n * 160;
    float ms0 = mrow[lane], ms1 = mrow[32 + lane];
    float v0 = mrow[64 + lane * 3 + 0];
    float v1 = mrow[64 + lane * 3 + 1];
    float v2 = mrow[64 + lane * 3 + 2];
    float n00 = fabsf(ms0), n01 = fabsf(ms1);
    float n02 = sqrtf(v0 * v0 + v1 * v1 + v2 * v2);
    float s = n00 + n01 + n02;
    float s2 = n00 * n00 + n01 * n01 + n02 * n02;
#pragma unroll
    for (int o = 16; o; o >>= 1) {
        s  += __shfl_xor_sync(0xffffffffu, s, o);
        s2 += __shfl_xor_sync(0xffffffffu, s2, o);
    }
    float mu = s * (1.f / 96.f);
    float var = s2 * (1.f / 96.f) - mu * mu;
    float rstd = rsqrtf(var + 1e-5f);
    sX[w][lane]      = (n00 - mu) * rstd * ln_g[lane]      + ln_b[lane];
    sX[w][lane + 32] = (n01 - mu) * rstd * ln_g[lane + 32] + ln_b[lane + 32];
    sX[w][lane + 64] = (n02 - mu) * rstd * ln_g[lane + 64] + ln_b[lane + 64];
    __syncwarp();
#pragma unroll
    for (int t = 0; t < 3; t++) {
        int jp = lane + t * 32;
        float hs = b1[jp];
        for (int j = 0; j < 96; j++) hs += sX[w][j] * W1[j * 96 + jp];
        sH[w][jp] = hs / (1.f + expf(-hs));
    }
    __syncwarp();
    float n0arr[3] = {n00, n01, n02};
    float f[3];
#pragma unroll
    for (int t = 0; t < 3; t++) {
        int jp = lane + t * 32;
        float gs = b2[jp];
        for (int j = 0; j < 96; j++) gs += sH[w][j] * W2[j * 96 + jp];
        float gg = gs / (1.f + expf(-gs));
        f[t] = gg / (n0arr[t] + 1e-6f);
    }
    out[n * 160 + lane]      = ms0 * f[0];
    out[n * 160 + 32 + lane] = ms1 * f[1];
    out[n * 160 + 64 + lane * 3 + 0] = v0 * f[2];
    out[n * 160 + 64 + lane * 3 + 1] = v1 * f[2];
    out[n * 160 + 64 + lane * 3 + 2] = v2 * f[2];
}

// ---------------- launch ----------------------------------------------------------------
extern "C" void kernel_launch(void* const* d_in, const int* in_sizes, int n_in,
                              void* d_out, int out_size) {
    const float* pseduo_x = (const float*)d_in[0];
    const float* rbf   = (const float*)d_in[1];
    const float* rsh   = (const float*)d_in[2];
    const int*   ei    = (const int*)d_in[3];
    const float* Wq_s  = (const float*)d_in[4];
    const float* Wq_v  = (const float*)d_in[5];
    const float* Wk_s  = (const float*)d_in[6];
    const float* Wk_v  = (const float*)d_in[7];
    const float* Wp_s  = (const float*)d_in[8];
    const float* Wp_v  = (const float*)d_in[9];
    const float* Wrbf  = (const float*)d_in[10];
    const float* Wv_s  = (const float*)d_in[11];
    const float* Wv_v  = (const float*)d_in[12];
    const float* Wm_s  = (const float*)d_in[13];
    const float* Wm_v  = (const float*)d_in[14];
    const float* ln_g  = (const float*)d_in[15];
    const float* ln_b  = (const float*)d_in[16];
    const float* W1    = (const float*)d_in[17];
    const float* b1    = (const float*)d_in[18];
    const float* W2    = (const float*)d_in[19];
    const float* b2    = (const float*)d_in[20];
    float* out = (float*)d_out;

    void* p;
    cudaGetSymbolAddress(&p, g_S);   float* S   = (float*)p;
    cudaGetSymbolAddress(&p, g_V);   float* V   = (float*)p;
    cudaGetSymbolAddress(&p, g_agg); float* AGG = (float*)p;
    cudaGetSymbolAddress(&p, g_m);   float* M   = (float*)p;
    cudaGetSymbolAddress(&p, g_Wts); float* Wts = (float*)p;
    cudaGetSymbolAddress(&p, g_Wtv); float* Wtv = (float*)p;
    cudaGetSymbolAddress(&p, g_Wcs); float* Wcs = (float*)p;
    cudaGetSymbolAddress(&p, g_Wcv); float* Wcv = (float*)p;

    k_init<<<32, 256>>>();
    k_pack<<<504, 256>>>(Wq_s, Wq_v, Wk_s, Wk_v, Wp_s, Wp_v, Wv_s, Wv_v, Wm_s, Wm_v);

    // node scalar proj: [8192,64] @ [64,1088] -> g_S
    k_gemm<<<dim3(17, 128, 1), 256>>>(pseduo_x, 160, 1, 0, Wts, 1088,
                                      S, 1088, 1, 0, 0, 64, 1088);
    // node vector proj: 3 x [8192,32] @ [32,576] -> g_V
    k_gemm<<<dim3(9, 128, 3), 256>>>(pseduo_x + 64, 160, 3, 1, Wtv, 576,
                                     V, 1728, 3, 1, 0, 32, 576);
    k_qkself<<<8192, 256>>>(pseduo_x);

    // CSR over dst
    k_hist<<<256, 256>>>(ei);
    k_scan<<<1, 1024>>>();
    k_scatter<<<256, 256>>>(ei);

    // per-edge features
    k_edgeprep<<<8192, 256>>>(rbf, rsh, ei, Wrbf);

    // fused attention + aggregation
    k_attn_agg<<<8192, 256>>>(pseduo_x, ei);

    // folded value+message projection: agg @ Wc -> m
    k_gemm<<<dim3(1, 128, 1), 256>>>(AGG, 1280, 1, 0, Wcs, 64,
                                     M, 160, 1, 0, 0, 512, 64);
    k_gemm<<<dim3(1, 128, 3), 256>>>(AGG + 512, 1280, 1, 256, Wcv, 32,
                                     M, 160, 3, 1, 64, 256, 32);

    k_normgate<<<1024, 256>>>(ln_g, ln_b, W1, b1, W2, b2, out);
}

// round 3
// speedup vs baseline: 2.6795x; 1.1024x over previous
#include <cuda_runtime.h>
#include <math.h>
#include <float.h>

#define NN 8192
#define NE 65536

#define INV_SQRT128 0.08838834764831843f
#define INV_SQRT512 0.04419417382415922f
#define INV_SQRT3   0.5773502691896258f
#define INV_SQRT160 0.07905694150420949f
#define INV_SQRT32  0.17677669529663687f

#define SC_S   (0.125f * INV_SQRT128 * INV_SQRT160)
#define SC_V   (INV_SQRT32 * 0.125f * INV_SQRT160)
#define SC_P_S (INV_SQRT128)
#define SC_P_V (0.125f)
#define SC_C_S (0.125f * INV_SQRT512)
#define SC_C_V (0.125f * 0.0625f)

// ---------------- scratch ------------------------------------------------------
__device__ float g_xT[160 * NN];      // transposed node features
__device__ float g_S[NN * 1088];      // tk_s(512) | tself_s(512) | PA_s(32) | PB_s(32)
__device__ float g_V[NN * 1728];      // (col*3+c): tk_v | tself_v | PAv | PBv
__device__ float g_QKself[NN * 8];
__device__ float g_feat[NE * 160];
__device__ float g_logit[NE * 8];     // fallback only (deg > 128)
__device__ float g_agg[NN * 1280];
__device__ float g_m[NN * 160];
__device__ int   g_cnt[NN];
__device__ int   g_offs[NN + 1];
__device__ int   g_cursor[NN];
__device__ int   g_elist[NE];
__device__ float g_Wts[64 * 1088];
__device__ float g_Wtv[32 * 576];
__device__ float g_Wcs[512 * 64];
__device__ float g_Wcv[256 * 32];

// ---------------- weight packing / grams (smem staged) --------------------------
__global__ void __launch_bounds__(256) k_pack2(
        const float* __restrict__ Wq_s, const float* __restrict__ Wq_v,
        const float* __restrict__ Wk_s, const float* __restrict__ Wk_v,
        const float* __restrict__ Wp_s, const float* __restrict__ Wp_v,
        const float* __restrict__ Wv_s, const float* __restrict__ Wv_v,
        const float* __restrict__ Wm_s, const float* __restrict__ Wm_v) {
    __shared__ float sm[8192];
    int b = blockIdx.x, tid = threadIdx.x;
    if (b < 16) {                       // scalar grams: cross (self=0) / self (self=1)
        int h = b & 7, self = b >> 3;
        float* Q = sm; float* Kx = sm + 4096;
        for (int i = tid; i < 4096; i += 256) {
            int a = i >> 6, j = i & 63;
            Q[i]  = Wq_s[a * 512 + h * 64 + j];
            int kr = self ? a : (64 + a);
            Kx[i] = Wk_s[kr * 512 + h * 64 + j];
        }
        __syncthreads();
        for (int i = tid; i < 4096; i += 256) {
            int a = i & 63, bb = i >> 6;
            float s = 0.f;
            for (int j = 0; j < 64; j++) s += Q[a * 64 + j] * Kx[bb * 64 + j];
            g_Wts[bb * 1088 + self * 512 + h * 64 + a] = s * SC_S;
        }
    } else if (b < 32) {                // vector grams
        int h = (b - 16) & 7, self = (b - 16) >> 3;
        float* Q = sm; float* Kx = sm + 1024;
        for (int i = tid; i < 1024; i += 256) {
            int a = i >> 5, j = i & 31;
            Q[i]  = Wq_v[a * 256 + h * 32 + j];
            int kr = self ? a : (32 + a);
            Kx[i] = Wk_v[kr * 256 + h * 32 + j];
        }
        __syncthreads();
        for (int i = tid; i < 1024; i += 256) {
            int a = i & 31, bb = i >> 5;
            float s = 0.f;
            for (int j = 0; j < 32; j++) s += Q[a * 32 + j] * Kx[bb * 32 + j];
            g_Wtv[bb * 576 + self * 256 + h * 32 + a] = s * SC_V;
        }
    } else if (b < 40) {                // Wcs = Wv_s x Wm_s per head
        int h = b - 32;
        float* V = sm; float* M = sm + 4096;
        for (int i = tid; i < 4096; i += 256) {
            int k = i >> 6, j = i & 63;
            V[i] = Wv_s[k * 512 + h * 64 + j];
            M[i] = Wm_s[(h * 64 + k) * 64 + j];   // M[j][d] with (k=j, j=d)
        }
        __syncthreads();
        for (int i = tid; i < 4096; i += 256) {
            int d = i & 63, k = i >> 6;
            float s = 0.f;
            for (int j = 0; j < 64; j++) s += V[k * 64 + j] * M[j * 64 + d];
            g_Wcs[(h * 64 + k) * 64 + d] = s * SC_C_S;
        }
    } else if (b < 48) {                // Wcv = (Wv_v fold) x Wm_v per head
        int h = b - 40;
        float* V = sm; float* M = sm + 1024;
        for (int i = tid; i < 1024; i += 256) {
            int k = i >> 5, j = i & 31;
            V[i] = Wv_v[k * 256 + h * 32 + j] + Wv_v[(32 + k) * 256 + h * 32 + j];
            M[i] = Wm_v[(h * 32 + k) * 32 + j];
        }
        __syncthreads();
        for (int i = tid; i < 1024; i += 256) {
            int d = i & 31, k = i >> 5;
            float s = 0.f;
            for (int j = 0; j < 32; j++) s += V[k * 32 + j] * M[j * 32 + d];
            g_Wcv[(h * 32 + k) * 32 + d] = s * SC_C_V;
        }
    } else {                            // Wp copies
        for (int i = tid; i < 4096; i += 256) {
            int bb = i >> 6, c = i & 63;
            float w = (c < 32) ? Wp_s[bb * 32 + c] : Wp_s[(64 + bb) * 32 + (c - 32)];
            g_Wts[bb * 1088 + 1024 + c] = w * SC_P_S;
        }
        for (int i = tid; i < 2048; i += 256) {
            int bb = i >> 6, c = i & 63;
            float w = (c < 32) ? Wp_v[bb * 32 + c] : Wp_v[(32 + bb) * 32 + (c - 32)];
            g_Wtv[bb * 576 + 512 + c] = w * SC_P_V;
        }
    }
}

// ---------------- transpose x -> xT [160][8192] ---------------------------------
__global__ void k_xT(const float* __restrict__ x, float* __restrict__ xT) {
    __shared__ float t[32][33];
    int tx = threadIdx.x, ty = threadIdx.y;
    int n0 = blockIdx.x * 32, t0 = blockIdx.y * 32;
#pragma unroll
    for (int i = 0; i < 32; i += 8)
        t[ty + i][tx] = x[(size_t)(n0 + ty + i) * 160 + t0 + tx];
    __syncthreads();
#pragma unroll
    for (int i = 0; i < 32; i += 8)
        xT[(size_t)(t0 + ty + i) * 8192 + n0 + tx] = t[tx][ty + i];
}

// ---------------- specialized full-K GEMM: C = x @ W -----------------------------
// AT: transposed A [rows][8192]; row = baseRow + z + k*rowStride
// COLMUL=1: C[m*cRow + col]; COLMUL=3: C[m*cRow + col*3 + z]
template<int K, int COLMUL>
__global__ void __launch_bounds__(256) k_gemmT(
        const float* __restrict__ AT, int baseRow, int rowStride,
        const float* __restrict__ W, int N,
        float* __restrict__ C, int cRow) {
    __shared__ __align__(16) float As[K * 128];
    __shared__ __align__(16) float Ws[K * 64];
    int tid = threadIdx.x;
    int n0 = blockIdx.x * 64, m0 = blockIdx.y * 128;
    int z = blockIdx.z;
#pragma unroll
    for (int r = 0; r < (K * 128) / 1024; r++) {
        int idx = tid + r * 256;
        int k = idx >> 5, mp = idx & 31;
        *(float4*)&As[k * 128 + mp * 4] =
            *(const float4*)&AT[(size_t)(baseRow + z + k * rowStride) * 8192 + m0 + mp * 4];
    }
#pragma unroll
    for (int r = 0; r < (K * 64) / 1024; r++) {
        int idx = tid + r * 256;
        int k = idx >> 4, j = idx & 15;
        *(float4*)&Ws[k * 64 + j * 4] = *(const float4*)&W[(size_t)k * N + n0 + j * 4];
    }
    __syncthreads();
    int ty = tid >> 4, tx = tid & 15;
    float acc[8][4] = {};
#pragma unroll 8
    for (int k = 0; k < K; k++) {
        float4 a0 = *(const float4*)&As[k * 128 + ty * 8];
        float4 a1 = *(const float4*)&As[k * 128 + ty * 8 + 4];
        float4 b4 = *(const float4*)&Ws[k * 64 + tx * 4];
        float av[8] = {a0.x, a0.y, a0.z, a0.w, a1.x, a1.y, a1.z, a1.w};
        float bv[4] = {b4.x, b4.y, b4.z, b4.w};
#pragma unroll
        for (int i = 0; i < 8; i++)
#pragma unroll
            for (int j = 0; j < 4; j++)
                acc[i][j] += av[i] * bv[j];
    }
    if (COLMUL == 1) {
#pragma unroll
        for (int i = 0; i < 8; i++) {
            float4 v = make_float4(acc[i][0], acc[i][1], acc[i][2], acc[i][3]);
            *(float4*)&C[(size_t)(m0 + ty * 8 + i) * cRow + n0 + tx * 4] = v;
        }
    } else {
#pragma unroll
        for (int i = 0; i < 8; i++)
#pragma unroll
            for (int j = 0; j < 4; j++)
                C[(size_t)(m0 + ty * 8 + i) * cRow + (n0 + tx * 4 + j) * 3 + z] = acc[i][j];
    }
}

// ---------------- generic tiled fp32 GEMM (final projections) --------------------
__global__ void __launch_bounds__(256) k_gemm(
    const float* __restrict__ A, int aRow, int aCol, int aComp,
    const float* __restrict__ W, int WO,
    float* __restrict__ C, int cRow, int cCol, int cComp, int ccol0,
    int K, int NC) {
    __shared__ __align__(16) float As[32 * 68];
    __shared__ __align__(16) float Ws[32 * 68];
    int tid = threadIdx.x;
    int m0 = blockIdx.y * 64;
    int n0 = blockIdx.x * 64;
    int comp = blockIdx.z;
    const float* Ab = A + (size_t)comp * aComp;
    float acc[4][4] = {};
    int ty = tid >> 4, tx = tid & 15;

    for (int k0 = 0; k0 < K; k0 += 32) {
#pragma unroll
        for (int r = 0; r < 8; r++) {
            int l = tid + r * 256;
            int kk = l & 31, mm = l >> 5;
            As[kk * 68 + mm] = Ab[(size_t)(m0 + mm) * aRow + (size_t)(k0 + kk) * aCol];
        }
#pragma unroll
        for (int r = 0; r < 8; r++) {
            int l = tid + r * 256;
            int kk = l >> 6, jj = l & 63;
            int col = n0 + jj;
            Ws[kk * 68 + jj] = (col < NC) ? W[(size_t)(k0 + kk) * WO + col] : 0.f;
        }
        __syncthreads();
#pragma unroll
        for (int k = 0; k < 32; k++) {
            float4 a4 = *(const float4*)&As[k * 68 + ty * 4];
            float4 b4 = *(const float4*)&Ws[k * 68 + tx * 4];
            float av[4] = {a4.x, a4.y, a4.z, a4.w};
            float bv[4] = {b4.x, b4.y, b4.z, b4.w};
#pragma unroll
            for (int i = 0; i < 4; i++)
#pragma unroll
                for (int j = 0; j < 4; j++)
                    acc[i][j] += av[i] * bv[j];
        }
        __syncthreads();
    }
#pragma unroll
    for (int i = 0; i < 4; i++) {
        int m = m0 + ty * 4 + i;
#pragma unroll
        for (int j = 0; j < 4; j++) {
            int col = n0 + tx * 4 + j;
            if (col < NC)
                C[(size_t)m * cRow + (size_t)comp * cComp + ccol0 + (size_t)col * cCol] = acc[i][j];
        }
    }
}

// ---------------- per-(node,head) self term ---------------------------------------
__global__ void __launch_bounds__(256) k_qkself(const float* __restrict__ x) {
    int wid = blockIdx.x * 8 + (threadIdx.x >> 5);
    int lane = threadIdx.x & 31;
    int n = wid >> 3, h = wid & 7;
    const float* ts = g_S + n * 1088 + 512 + h * 64;
    const float* tv = g_V + (size_t)n * 1728 + 768 + h * 96;
    const float* xr = x + (size_t)n * 160;
    float a = ts[lane] * xr[lane] + ts[32 + lane] * xr[32 + lane];
#pragma unroll
    for (int t = 0; t < 3; t++) {
        int j = lane + t * 32;
        a += tv[j] * xr[64 + j];
    }
#pragma unroll
    for (int o = 16; o; o >>= 1) a += __shfl_xor_sync(0xffffffffu, a, o);
    if (lane == 0) g_QKself[n * 8 + h] = a;
}

// ---------------- init / CSR ------------------------------------------------------
__global__ void k_init() {
    int i = blockIdx.x * 256 + threadIdx.x;
    if (i < NN) g_cnt[i] = 0;
}

__global__ void k_hist(const int* __restrict__ ei) {
    int e = blockIdx.x * 256 + threadIdx.x;
    if (e < NE) atomicAdd(&g_cnt[ei[NE + e]], 1);
}

__global__ void __launch_bounds__(1024) k_scan() {
    __shared__ int wsum[32];
    int tid = threadIdx.x;
    int base = tid * 8;
    int loc[8]; int tot = 0;
#pragma unroll
    for (int i = 0; i < 8; i++) { loc[i] = tot; tot += g_cnt[base + i]; }
    int lane = tid & 31, w = tid >> 5;
    int incl = tot;
#pragma unroll
    for (int o = 1; o < 32; o <<= 1) {
        int y = __shfl_up_sync(0xffffffffu, incl, o);
        if (lane >= o) incl += y;
    }
    if (lane == 31) wsum[w] = incl;
    int excl = incl - tot;
    __syncthreads();
    if (w == 0) {
        int t = wsum[lane];
        int i2 = t;
#pragma unroll
        for (int o = 1; o < 32; o <<= 1) {
            int y = __shfl_up_sync(0xffffffffu, i2, o);
            if (lane >= o) i2 += y;
        }
        wsum[lane] = i2 - t;
    }
    __syncthreads();
    int off = wsum[w] + excl;
#pragma unroll
    for (int i = 0; i < 8; i++) {
        int o2 = off + loc[i];
        g_offs[base + i] = o2;
        g_cursor[base + i] = o2;
    }
    if (tid == 1023) g_offs[NN] = NE;
}

__global__ void k_scatter(const int* __restrict__ ei) {
    int e = blockIdx.x * 256 + threadIdx.x;
    if (e < NE) {
        int pos = atomicAdd(&g_cursor[ei[NE + e]], 1);
        g_elist[pos] = e;
    }
}

// ---------------- per-edge sph -> feat ---------------------------------------------
__global__ void __launch_bounds__(256) k_edgeprep(const float* __restrict__ rbf,
                                                  const float* __restrict__ rsh,
                                                  const int* __restrict__ ei,
                                                  const float* __restrict__ Wrbf) {
    __shared__ float sW[1024];
    int tid = threadIdx.x;
    for (int l = tid; l < 1024; l += 256) sW[l] = Wrbf[l];
    __syncthreads();
    int e = blockIdx.x * 8 + (tid >> 5);
    int lane = tid & 31;
    int src = ei[e], dst = ei[NE + e];
    int d = lane;
    float ps  = g_S[src * 1088 + 1024 + d] + g_S[dst * 1088 + 1056 + d];
    float pv0 = g_V[(size_t)src * 1728 + 1536 + d * 3 + 0] + g_V[(size_t)dst * 1728 + 1632 + d * 3 + 0];
    float pv1 = g_V[(size_t)src * 1728 + 1536 + d * 3 + 1] + g_V[(size_t)dst * 1728 + 1632 + d * 3 + 1];
    float pv2 = g_V[(size_t)src * 1728 + 1536 + d * 3 + 2] + g_V[(size_t)dst * 1728 + 1632 + d * 3 + 2];
    float rval = (lane < 16) ? rbf[e * 16 + lane] : 0.f;
    float scal_s = 0.f, scal_v = 0.f;
#pragma unroll
    for (int b = 0; b < 16; b++) {
        float rb = __shfl_sync(0xffffffffu, rval, b);
        scal_s += rb * sW[b * 64 + d];
        scal_v += rb * sW[b * 64 + 32 + d];
    }
    float rs  = rsh[e * 128 + d];
    float rv0 = rsh[e * 128 + 32 + d * 3 + 0];
    float rv1 = rsh[e * 128 + 32 + d * 3 + 1];
    float rv2 = rsh[e * 128 + 32 + d * 3 + 2];
    float sph_s = rs * scal_s * ps;
    float sv0 = rv0 * scal_v * pv0;
    float sv1 = rv1 * scal_v * pv1;
    float sv2 = rv2 * scal_v * pv2;
    float* f = g_feat + (size_t)e * 160;
    f[d]      = sph_s * sph_s;
    f[32 + d] = (sv0 * sv0 + sv1 * sv1 + sv2 * sv2) * INV_SQRT3;
    f[64 + d * 3 + 0] = sph_s * sv0;
    f[64 + d * 3 + 1] = sph_s * sv1;
    f[64 + d * 3 + 2] = sph_s * sv2;
}

// ---------------- fused logits + softmax + aggregation ------------------------------
__global__ void __launch_bounds__(256) k_attn_agg(const float* __restrict__ x,
                                                  const int* __restrict__ ei) {
    int n = blockIdx.x;
    int tid = threadIdx.x;
    int wid = tid >> 5, lane = tid & 31;
    int h = lane >> 2, p = lane & 3;

    __shared__ float s_tk[1280];
    __shared__ float s_x[8][160];
    __shared__ float s_lg[128 * 8];
    __shared__ float s_wmax[64];
    __shared__ float s_max[8], s_den[8], s_inv[8];
    __shared__ float s_feat[32 * 160];
    __shared__ float s_attn[32 * 8];
    __shared__ int   s_e[32];

    for (int i = tid; i < 320; i += 256)
        ((float4*)s_tk)[i] = (i < 128) ? ((const float4*)(g_S + n * 1088))[i]
                                       : ((const float4*)(g_V + (size_t)n * 1728))[i - 128];
    if (tid < 8) s_den[tid] = 0.f;
    __syncthreads();

    int s0 = g_offs[n], deg = g_offs[n + 1] - s0;
    float* lg = (deg <= 128) ? s_lg : (g_logit + (size_t)s0 * 8);

    // pass 1: logits
    float mymax = -FLT_MAX;
    for (int idx = wid; idx < deg; idx += 8) {
        int e = g_elist[s0 + idx];
        int src = ei[e];
        const float4* xs = (const float4*)(x + (size_t)src * 160);
        ((float4*)s_x[wid])[lane] = xs[lane];
        if (lane < 8) ((float4*)s_x[wid])[32 + lane] = xs[32 + lane];
        __syncwarp();
        const float* xr = s_x[wid];
        float a = 0.f;
#pragma unroll
        for (int tt = 0; tt < 40; tt++) {
            int t = p * 40 + tt;
            int f = (t < 64) ? (h * 64 + t) : (512 + h * 96 + (t - 64));
            a += s_tk[f] * xr[t];
        }
        a += __shfl_xor_sync(0xffffffffu, a, 1);
        a += __shfl_xor_sync(0xffffffffu, a, 2);
        if (p == 0) {
            a += g_QKself[src * 8 + h];
            lg[idx * 8 + h] = a;
            mymax = fmaxf(mymax, a);
        }
        __syncwarp();
    }
    if (p == 0) s_wmax[wid * 8 + h] = mymax;
    __syncthreads();
    if (tid < 8) {
        float m = -FLT_MAX;
#pragma unroll
        for (int w = 0; w < 8; w++) m = fmaxf(m, s_wmax[w * 8 + tid]);
        s_max[tid] = m;
    }
    __syncthreads();

    for (int i = tid; i < deg * 8; i += 256) {
        float ex = expf(lg[i] - s_max[i & 7]);
        lg[i] = ex;
        atomicAdd(&s_den[i & 7], ex);
    }
    __syncthreads();
    if (tid < 8) {
        float dnm = s_den[tid];
        s_inv[tid] = (dnm > 0.f) ? 1.f / dnm : 0.f;
    }

    float acc[5] = {0, 0, 0, 0, 0};
    int fidx[5], hd[5], el[5];
#pragma unroll
    for (int i = 0; i < 5; i++) {
        int e2 = tid + i * 256;
        el[i] = e2;
        if (e2 < 512) { hd[i] = e2 >> 6; fidx[i] = e2 & 63; }
        else {
            int r = e2 - 512;
            int k = r & 31, hh = (r >> 5) & 7, c = r >> 8;
            hd[i] = hh; fidx[i] = 64 + k * 3 + c;
        }
    }

    for (int cs = 0; cs < deg; cs += 32) {
        int nc = min(32, deg - cs);
        __syncthreads();
        if (tid < nc) s_e[tid] = g_elist[s0 + cs + tid];
        for (int i = tid; i < nc * 8; i += 256)
            s_attn[i] = lg[(cs + (i >> 3)) * 8 + (i & 7)] * s_inv[i & 7];
        __syncthreads();
        for (int q = tid; q < nc * 40; q += 256)
            ((float4*)s_feat)[q] = ((const float4*)(g_feat + (size_t)s_e[q / 40] * 160))[q % 40];
        __syncthreads();
        for (int j = 0; j < nc; j++) {
            const float* fr = s_feat + j * 160;
            const float* ar = s_attn + j * 8;
#pragma unroll
            for (int i = 0; i < 5; i++)
                acc[i] += ar[hd[i]] * fr[fidx[i]];
        }
    }
#pragma unroll
    for (int i = 0; i < 5; i++) g_agg[(size_t)n * 1280 + el[i]] = acc[i];
}

// ---------------- NormGate + output (32 nodes/block, W1 in smem) ---------------------
__global__ void __launch_bounds__(256) k_normgate(const float* __restrict__ ln_g,
                                                  const float* __restrict__ ln_b,
                                                  const float* __restrict__ W1,
                                                  const float* __restrict__ b1,
                                                  const float* __restrict__ W2,
                                                  const float* __restrict__ b2,
                                                  float* __restrict__ out) {
    __shared__ float sW1[96 * 96];
    __shared__ float sX[8][96];
    __shared__ float sH[8][96];
    int tid = threadIdx.x;
    int w = tid >> 5, lane = tid & 31;
    for (int i = tid; i < 9216; i += 256) sW1[i] = W1[i];
    __syncthreads();

    for (int sub = 0; sub < 4; sub++) {
        int n = blockIdx.x * 32 + w * 4 + sub;
        const float* mrow = g_m + (size_t)n * 160;
        float ms0 = mrow[lane], ms1 = mrow[32 + lane];
        float v0 = mrow[64 + lane * 3 + 0];
        float v1 = mrow[64 + lane * 3 + 1];
        float v2 = mrow[64 + lane * 3 + 2];
        float n00 = fabsf(ms0), n01 = fabsf(ms1);
        float n02 = sqrtf(v0 * v0 + v1 * v1 + v2 * v2);
        float s = n00 + n01 + n02;
        float s2 = n00 * n00 + n01 * n01 + n02 * n02;
#pragma unroll
        for (int o = 16; o; o >>= 1) {
            s  += __shfl_xor_sync(0xffffffffu, s, o);
            s2 += __shfl_xor_sync(0xffffffffu, s2, o);
        }
        float mu = s * (1.f / 96.f);
        float var = s2 * (1.f / 96.f) - mu * mu;
        float rstd = rsqrtf(var + 1e-5f);
        sX[w][lane]      = (n00 - mu) * rstd * ln_g[lane]      + ln_b[lane];
        sX[w][lane + 32] = (n01 - mu) * rstd * ln_g[lane + 32] + ln_b[lane + 32];
        sX[w][lane + 64] = (n02 - mu) * rstd * ln_g[lane + 64] + ln_b[lane + 64];
        __syncwarp();
#pragma unroll
        for (int t = 0; t < 3; t++) {
            int jp = lane + t * 32;
            float hs = b1[jp];
            for (int j = 0; j < 96; j++) hs += sX[w][j] * sW1[j * 96 + jp];
            sH[w][jp] = hs / (1.f + expf(-hs));
        }
        __syncwarp();
        float n0arr[3] = {n00, n01, n02};
        float f[3];
#pragma unroll
        for (int t = 0; t < 3; t++) {
            int jp = lane + t * 32;
            float gs = b2[jp];
            for (int j = 0; j < 96; j++) gs += sH[w][j] * W2[j * 96 + jp];
            float gg = gs / (1.f + expf(-gs));
            f[t] = gg / (n0arr[t] + 1e-6f);
        }
        out[n * 160 + lane]      = ms0 * f[0];
        out[n * 160 + 32 + lane] = ms1 * f[1];
        out[n * 160 + 64 + lane * 3 + 0] = v0 * f[2];
        out[n * 160 + 64 + lane * 3 + 1] = v1 * f[2];
        out[n * 160 + 64 + lane * 3 + 2] = v2 * f[2];
        __syncwarp();
    }
}

// ---------------- launch ----------------------------------------------------------------
extern "C" void kernel_launch(void* const* d_in, const int* in_sizes, int n_in,
                              void* d_out, int out_size) {
    const float* pseduo_x = (const float*)d_in[0];
    const float* rbf   = (const float*)d_in[1];
    const float* rsh   = (const float*)d_in[2];
    const int*   ei    = (const int*)d_in[3];
    const float* Wq_s  = (const float*)d_in[4];
    const float* Wq_v  = (const float*)d_in[5];
    const float* Wk_s  = (const float*)d_in[6];
    const float* Wk_v  = (const float*)d_in[7];
    const float* Wp_s  = (const float*)d_in[8];
    const float* Wp_v  = (const float*)d_in[9];
    const float* Wrbf  = (const float*)d_in[10];
    const float* Wv_s  = (const float*)d_in[11];
    const float* Wv_v  = (const float*)d_in[12];
    const float* Wm_s  = (const float*)d_in[13];
    const float* Wm_v  = (const float*)d_in[14];
    const float* ln_g  = (const float*)d_in[15];
    const float* ln_b  = (const float*)d_in[16];
    const float* W1    = (const float*)d_in[17];
    const float* b1    = (const float*)d_in[18];
    const float* W2    = (const float*)d_in[19];
    const float* b2    = (const float*)d_in[20];
    float* out = (float*)d_out;

    void* p;
    cudaGetSymbolAddress(&p, g_xT);  float* XT  = (float*)p;
    cudaGetSymbolAddress(&p, g_S);   float* S   = (float*)p;
    cudaGetSymbolAddress(&p, g_V);   float* V   = (float*)p;
    cudaGetSymbolAddress(&p, g_agg); float* AGG = (float*)p;
    cudaGetSymbolAddress(&p, g_m);   float* M   = (float*)p;
    cudaGetSymbolAddress(&p, g_Wts); float* Wts = (float*)p;
    cudaGetSymbolAddress(&p, g_Wtv); float* Wtv = (float*)p;
    cudaGetSymbolAddress(&p, g_Wcs); float* Wcs = (float*)p;
    cudaGetSymbolAddress(&p, g_Wcv); float* Wcv = (float*)p;

    k_init<<<32, 256>>>();
    k_pack2<<<49, 256>>>(Wq_s, Wq_v, Wk_s, Wk_v, Wp_s, Wp_v, Wv_s, Wv_v, Wm_s, Wm_v);
    k_xT<<<dim3(256, 5), dim3(32, 8)>>>(pseduo_x, XT);

    // node projections (full-K resident GEMM)
    k_gemmT<64, 1><<<dim3(17, 64, 1), 256>>>(XT, 0, 1, Wts, 1088, S, 1088);
    k_gemmT<32, 3><<<dim3(9, 64, 3), 256>>>(XT, 64, 3, Wtv, 576, V, 1728);
    k_qkself<<<8192, 256>>>(pseduo_x);

    // CSR over dst
    k_hist<<<256, 256>>>(ei);
    k_scan<<<1, 1024>>>();
    k_scatter<<<256, 256>>>(ei);

    // per-edge features
    k_edgeprep<<<8192, 256>>>(rbf, rsh, ei, Wrbf);

    // fused attention + aggregation
    k_attn_agg<<<8192, 256>>>(pseduo_x, ei);

    // folded value+message projection
    k_gemm<<<dim3(1, 128, 1), 256>>>(AGG, 1280, 1, 0, Wcs, 64,
                                     M, 160, 1, 0, 0, 512, 64);
    k_gemm<<<dim3(1, 128, 3), 256>>>(AGG + 512, 1280, 1, 256, Wcv, 32,
                                     M, 160, 3, 1, 64, 256, 32);

    k_normgate<<<256, 256>>>(ln_g, ln_b, W1, b1, W2, b2, out);
}

// round 4
// speedup vs baseline: 3.0878x; 1.1524x over previous
#include <cuda_runtime.h>
#include <math.h>
#include <float.h>

#define NN 8192
#define NE 65536
#define VPLANE ((size_t)NN * 576)

#define INV_SQRT128 0.08838834764831843f
#define INV_SQRT512 0.04419417382415922f
#define INV_SQRT3   0.5773502691896258f
#define INV_SQRT160 0.07905694150420949f
#define INV_SQRT32  0.17677669529663687f

#define SC_S   (0.125f * INV_SQRT128 * INV_SQRT160)
#define SC_V   (INV_SQRT32 * 0.125f * INV_SQRT160)
#define SC_P_S (INV_SQRT128)
#define SC_P_V (0.125f)
#define SC_C_S (0.125f * INV_SQRT512)
#define SC_C_V (0.125f * 0.0625f)

typedef unsigned long long u64;

__device__ __forceinline__ void fma2(u64& d, u64 a, u64 b) {
    asm("fma.rn.f32x2 %0, %1, %2, %0;" : "+l"(d) : "l"(a), "l"(b));
}
__device__ __forceinline__ u64 dupf(float x) {
    u64 r; asm("mov.b64 %0, {%1, %1};" : "=l"(r) : "r"(__float_as_uint(x))); return r;
}

// ---------------- scratch ------------------------------------------------------
__device__ float g_xT[160 * NN];
__device__ float g_S[NN * 1088];          // tk_s 512 | tself_s 512 | PA_s 32 | PB_s 32
__device__ float g_V[3 * NN * 576];       // plane c: [n][ tk_v 256 | tself_v 256 | PAv 32 | PBv 32 ]
__device__ float g_QKself[NN * 8];
__device__ float g_feat[NE * 160];        // c0 64 | vec c*32+d (96)
__device__ float g_logit[NE * 8];         // fallback (deg > 64)
__device__ float g_agg[NN * 1280];
__device__ float g_m[NN * 160];
__device__ int   g_cnt[NN];
__device__ int   g_offs[NN + 1];
__device__ int   g_cursor[NN];
__device__ int   g_elist[NE];
__device__ float g_Wts[64 * 1088];
__device__ float g_Wtv[32 * 576];
__device__ float g_Wcs[512 * 64];
__device__ float g_Wcv[256 * 32];

// ---------------- weight packing / grams ----------------------------------------
__global__ void __launch_bounds__(256) k_pack2(
        const float* __restrict__ Wq_s, const float* __restrict__ Wq_v,
        const float* __restrict__ Wk_s, const float* __restrict__ Wk_v,
        const float* __restrict__ Wp_s, const float* __restrict__ Wp_v,
        const float* __restrict__ Wv_s, const float* __restrict__ Wv_v,
        const float* __restrict__ Wm_s, const float* __restrict__ Wm_v) {
    __shared__ float sm[8192];
    int b = blockIdx.x, tid = threadIdx.x;
    if (b < 16) {
        int h = b & 7, self = b >> 3;
        float* Q = sm; float* Kx = sm + 4096;
        for (int i = tid; i < 4096; i += 256) {
            int a = i >> 6, j = i & 63;
            Q[i]  = Wq_s[a * 512 + h * 64 + j];
            int kr = self ? a : (64 + a);
            Kx[i] = Wk_s[kr * 512 + h * 64 + j];
        }
        __syncthreads();
        for (int i = tid; i < 4096; i += 256) {
            int a = i & 63, bb = i >> 6;
            float s = 0.f;
            for (int j = 0; j < 64; j++) s += Q[a * 64 + j] * Kx[bb * 64 + j];
            g_Wts[bb * 1088 + self * 512 + h * 64 + a] = s * SC_S;
        }
    } else if (b < 32) {
        int h = (b - 16) & 7, self = (b - 16) >> 3;
        float* Q = sm; float* Kx = sm + 1024;
        for (int i = tid; i < 1024; i += 256) {
            int a = i >> 5, j = i & 31;
            Q[i]  = Wq_v[a * 256 + h * 32 + j];
            int kr = self ? a : (32 + a);
            Kx[i] = Wk_v[kr * 256 + h * 32 + j];
        }
        __syncthreads();
        for (int i = tid; i < 1024; i += 256) {
            int a = i & 31, bb = i >> 5;
            float s = 0.f;
            for (int j = 0; j < 32; j++) s += Q[a * 32 + j] * Kx[bb * 32 + j];
            g_Wtv[bb * 576 + self * 256 + h * 32 + a] = s * SC_V;
        }
    } else if (b < 40) {
        int h = b - 32;
        float* V = sm; float* M = sm + 4096;
        for (int i = tid; i < 4096; i += 256) {
            int k = i >> 6, j = i & 63;
            V[i] = Wv_s[k * 512 + h * 64 + j];
            M[i] = Wm_s[(h * 64 + k) * 64 + j];
        }
        __syncthreads();
        for (int i = tid; i < 4096; i += 256) {
            int d = i & 63, k = i >> 6;
            float s = 0.f;
            for (int j = 0; j < 64; j++) s += V[k * 64 + j] * M[j * 64 + d];
            g_Wcs[(h * 64 + k) * 64 + d] = s * SC_C_S;
        }
    } else if (b < 48) {
        int h = b - 40;
        float* V = sm; float* M = sm + 1024;
        for (int i = tid; i < 1024; i += 256) {
            int k = i >> 5, j = i & 31;
            V[i] = Wv_v[k * 256 + h * 32 + j] + Wv_v[(32 + k) * 256 + h * 32 + j];
            M[i] = Wm_v[(h * 32 + k) * 32 + j];
        }
        __syncthreads();
        for (int i = tid; i < 1024; i += 256) {
            int d = i & 31, k = i >> 5;
            float s = 0.f;
            for (int j = 0; j < 32; j++) s += V[k * 32 + j] * M[j * 32 + d];
            g_Wcv[(h * 32 + k) * 32 + d] = s * SC_C_V;
        }
    } else if (b == 48) {
        for (int i = tid; i < 4096; i += 256) {
            int bb = i >> 6, c = i & 63;
            float w = (c < 32) ? Wp_s[bb * 32 + c] : Wp_s[(64 + bb) * 32 + (c - 32)];
            g_Wts[bb * 1088 + 1024 + c] = w * SC_P_S;
        }
        for (int i = tid; i < 2048; i += 256) {
            int bb = i >> 6, c = i & 63;
            float w = (c < 32) ? Wp_v[bb * 32 + c] : Wp_v[(32 + bb) * 32 + (c - 32)];
            g_Wtv[bb * 576 + 512 + c] = w * SC_P_V;
        }
    } else {
        for (int i = tid; i < NN; i += 256) g_cnt[i] = 0;
    }
}

// ---------------- transpose x -> xT [160][8192] ----------------------------------
__global__ void k_xT(const float* __restrict__ x, float* __restrict__ xT) {
    __shared__ float t[32][33];
    int tx = threadIdx.x, ty = threadIdx.y;
    int n0 = blockIdx.x * 32, t0 = blockIdx.y * 32;
#pragma unroll
    for (int i = 0; i < 32; i += 8)
        t[ty + i][tx] = x[(size_t)(n0 + ty + i) * 160 + t0 + tx];
    __syncthreads();
#pragma unroll
    for (int i = 0; i < 32; i += 8)
        xT[(size_t)(t0 + ty + i) * 8192 + n0 + tx] = t[tx][ty + i];
}

// ---------------- full-K resident GEMM with f32x2 --------------------------------
// A row = baseRow + z + k*rowStride (in xT), output plane = C + z*planeStride
template<int K>
__global__ void __launch_bounds__(256) k_gemmT(
        const float* __restrict__ AT, int baseRow, int rowStride,
        const float* __restrict__ W, int N,
        float* __restrict__ C, int cRow, size_t planeStride) {
    __shared__ __align__(16) float As[K * 128];
    __shared__ __align__(16) float Ws[K * 64];
    int tid = threadIdx.x;
    int n0 = blockIdx.x * 64, m0 = blockIdx.y * 128;
    int z = blockIdx.z;
#pragma unroll
    for (int r = 0; r < (K * 128) / 1024; r++) {
        int idx = tid + r * 256;
        int k = idx >> 5, mp = idx & 31;
        *(float4*)&As[k * 128 + mp * 4] =
            *(const float4*)&AT[(size_t)(baseRow + z + k * rowStride) * 8192 + m0 + mp * 4];
    }
#pragma unroll
    for (int r = 0; r < (K * 64) / 1024; r++) {
        int idx = tid + r * 256;
        int k = idx >> 4, j = idx & 15;
        *(float4*)&Ws[k * 64 + j * 4] = *(const float4*)&W[(size_t)k * N + n0 + j * 4];
    }
    __syncthreads();
    int ty = tid >> 4, tx = tid & 15;
    u64 acc[4][4] = {};
#pragma unroll 8
    for (int k = 0; k < K; k++) {
        ulonglong2 a01 = *(const ulonglong2*)&As[k * 128 + ty * 8];
        ulonglong2 a23 = *(const ulonglong2*)&As[k * 128 + ty * 8 + 4];
        float4 b4 = *(const float4*)&Ws[k * 64 + tx * 4];
        u64 bb0 = dupf(b4.x), bb1 = dupf(b4.y), bb2 = dupf(b4.z), bb3 = dupf(b4.w);
        u64 ap[4] = {a01.x, a01.y, a23.x, a23.y};
#pragma unroll
        for (int q = 0; q < 4; q++) {
            fma2(acc[q][0], ap[q], bb0);
            fma2(acc[q][1], ap[q], bb1);
            fma2(acc[q][2], ap[q], bb2);
            fma2(acc[q][3], ap[q], bb3);
        }
    }
    float* Cb = C + (size_t)z * planeStride;
#pragma unroll
    for (int q = 0; q < 4; q++) {
        float2 c0 = *(float2*)&acc[q][0];
        float2 c1 = *(float2*)&acc[q][1];
        float2 c2 = *(float2*)&acc[q][2];
        float2 c3 = *(float2*)&acc[q][3];
        int r0 = m0 + ty * 8 + 2 * q;
        *(float4*)&Cb[(size_t)r0 * cRow + n0 + tx * 4]       = make_float4(c0.x, c1.x, c2.x, c3.x);
        *(float4*)&Cb[(size_t)(r0 + 1) * cRow + n0 + tx * 4] = make_float4(c0.y, c1.y, c2.y, c3.y);
    }
}

// ---------------- generic tiled fp32 GEMM (final projections) --------------------
__global__ void __launch_bounds__(256) k_gemm(
    const float* __restrict__ A, int aRow, int aCol, int aComp,
    const float* __restrict__ W, int WO,
    float* __restrict__ C, int cRow, int cCol, int cComp, int ccol0,
    int K, int NC) {
    __shared__ __align__(16) float As[32 * 68];
    __shared__ __align__(16) float Ws[32 * 68];
    int tid = threadIdx.x;
    int m0 = blockIdx.y * 64;
    int n0 = blockIdx.x * 64;
    int comp = blockIdx.z;
    const float* Ab = A + (size_t)comp * aComp;
    float acc[4][4] = {};
    int ty = tid >> 4, tx = tid & 15;

    for (int k0 = 0; k0 < K; k0 += 32) {
#pragma unroll
        for (int r = 0; r < 8; r++) {
            int l = tid + r * 256;
            int kk = l & 31, mm = l >> 5;
            As[kk * 68 + mm] = Ab[(size_t)(m0 + mm) * aRow + (size_t)(k0 + kk) * aCol];
        }
#pragma unroll
        for (int r = 0; r < 8; r++) {
            int l = tid + r * 256;
            int kk = l >> 6, jj = l & 63;
            int col = n0 + jj;
            Ws[kk * 68 + jj] = (col < NC) ? W[(size_t)(k0 + kk) * WO + col] : 0.f;
        }
        __syncthreads();
#pragma unroll
        for (int k = 0; k < 32; k++) {
            float4 a4 = *(const float4*)&As[k * 68 + ty * 4];
            float4 b4 = *(const float4*)&Ws[k * 68 + tx * 4];
            float av[4] = {a4.x, a4.y, a4.z, a4.w};
            float bv[4] = {b4.x, b4.y, b4.z, b4.w};
#pragma unroll
            for (int i = 0; i < 4; i++)
#pragma unroll
                for (int j = 0; j < 4; j++)
                    acc[i][j] += av[i] * bv[j];
        }
        __syncthreads();
    }
#pragma unroll
    for (int i = 0; i < 4; i++) {
        int m = m0 + ty * 4 + i;
#pragma unroll
        for (int j = 0; j < 4; j++) {
            int col = n0 + tx * 4 + j;
            if (col < NC)
                C[(size_t)m * cRow + (size_t)comp * cComp + ccol0 + (size_t)col * cCol] = acc[i][j];
        }
    }
}

// ---------------- self term: warp per node ----------------------------------------
__global__ void __launch_bounds__(256) k_qkself2(const float* __restrict__ x) {
    __shared__ float s_x[8][160];
    int tid = threadIdx.x;
    int wid = tid >> 5, lane = tid & 31;
    int n = blockIdx.x * 8 + wid;
    const float4* xs = (const float4*)(x + (size_t)n * 160);
    ((float4*)s_x[wid])[lane] = xs[lane];
    if (lane < 8) ((float4*)s_x[wid])[32 + lane] = xs[32 + lane];
    __syncwarp();
    const float* xr = s_x[wid];
    const float* Sb = g_S + (size_t)n * 1088 + 512;
#pragma unroll
    for (int h = 0; h < 8; h++) {
        float a = Sb[h * 64 + lane] * xr[lane]
                + Sb[h * 64 + 32 + lane] * xr[32 + lane];
#pragma unroll
        for (int c = 0; c < 3; c++)
            a += g_V[c * VPLANE + (size_t)n * 576 + 256 + h * 32 + lane]
                 * xr[64 + lane * 3 + c];
#pragma unroll
        for (int o = 16; o; o >>= 1) a += __shfl_xor_sync(0xffffffffu, a, o);
        if (lane == 0) g_QKself[n * 8 + h] = a;
    }
}

// ---------------- CSR --------------------------------------------------------------
__global__ void k_hist(const int* __restrict__ ei) {
    int e = blockIdx.x * 256 + threadIdx.x;
    if (e < NE) atomicAdd(&g_cnt[ei[NE + e]], 1);
}

__global__ void __launch_bounds__(1024) k_scan() {
    __shared__ int wsum[32];
    int tid = threadIdx.x;
    int base = tid * 8;
    int loc[8]; int tot = 0;
#pragma unroll
    for (int i = 0; i < 8; i++) { loc[i] = tot; tot += g_cnt[base + i]; }
    int lane = tid & 31, w = tid >> 5;
    int incl = tot;
#pragma unroll
    for (int o = 1; o < 32; o <<= 1) {
        int y = __shfl_up_sync(0xffffffffu, incl, o);
        if (lane >= o) incl += y;
    }
    if (lane == 31) wsum[w] = incl;
    int excl = incl - tot;
    __syncthreads();
    if (w == 0) {
        int t = wsum[lane];
        int i2 = t;
#pragma unroll
        for (int o = 1; o < 32; o <<= 1) {
            int y = __shfl_up_sync(0xffffffffu, i2, o);
            if (lane >= o) i2 += y;
        }
        wsum[lane] = i2 - t;
    }
    __syncthreads();
    int off = wsum[w] + excl;
#pragma unroll
    for (int i = 0; i < 8; i++) {
        int o2 = off + loc[i];
        g_offs[base + i] = o2;
        g_cursor[base + i] = o2;
    }
    if (tid == 1023) g_offs[NN] = NE;
}

__global__ void k_scatter(const int* __restrict__ ei) {
    int e = blockIdx.x * 256 + threadIdx.x;
    if (e < NE) {
        int pos = atomicAdd(&g_cursor[ei[NE + e]], 1);
        g_elist[pos] = e;
    }
}

// ---------------- per-edge sph -> feat ----------------------------------------------
__global__ void __launch_bounds__(256) k_edgeprep(const float* __restrict__ rbf,
                                                  const float* __restrict__ rsh,
                                                  const int* __restrict__ ei,
                                                  const float* __restrict__ Wrbf) {
    __shared__ float sW[1024];
    int tid = threadIdx.x;
    for (int l = tid; l < 1024; l += 256) sW[l] = Wrbf[l];
    __syncthreads();
    int e = blockIdx.x * 8 + (tid >> 5);
    int lane = tid & 31;
    int src = ei[e], dst = ei[NE + e];
    int d = lane;
    float ps = g_S[(size_t)src * 1088 + 1024 + d] + g_S[(size_t)dst * 1088 + 1056 + d];
    float pv[3];
#pragma unroll
    for (int c = 0; c < 3; c++)
        pv[c] = g_V[c * VPLANE + (size_t)src * 576 + 512 + d]
              + g_V[c * VPLANE + (size_t)dst * 576 + 544 + d];
    float rval = (lane < 16) ? rbf[e * 16 + lane] : 0.f;
    float scal_s = 0.f, scal_v = 0.f;
#pragma unroll
    for (int b = 0; b < 16; b++) {
        float rb = __shfl_sync(0xffffffffu, rval, b);
        scal_s += rb * sW[b * 64 + d];
        scal_v += rb * sW[b * 64 + 32 + d];
    }
    float rs = rsh[e * 128 + d];
    float sph_s = rs * scal_s * ps;
    float sv[3];
#pragma unroll
    for (int c = 0; c < 3; c++)
        sv[c] = rsh[e * 128 + 32 + d * 3 + c] * scal_v * pv[c];
    float* f = g_feat + (size_t)e * 160;
    f[d]      = sph_s * sph_s;
    f[32 + d] = (sv[0] * sv[0] + sv[1] * sv[1] + sv[2] * sv[2]) * INV_SQRT3;
#pragma unroll
    for (int c = 0; c < 3; c++)
        f[64 + c * 32 + d] = sph_s * sv[c];
}

// ---------------- fused attention + aggregation: warp per node ----------------------
__global__ void __launch_bounds__(256) k_attn_agg2(const float* __restrict__ x,
                                                   const int* __restrict__ ei) {
    __shared__ float s_x[8][160];
    __shared__ float s_lg[8][512];
    const unsigned F = 0xffffffffu;
    int tid = threadIdx.x;
    int wid = tid >> 5, lane = tid & 31;
    int n = blockIdx.x * 8 + wid;
    int h = lane >> 2, p = lane & 3;

    int s0 = g_offs[n], deg = g_offs[n + 1] - s0;
    float* lg = (deg <= 64) ? &s_lg[wid][0] : (g_logit + (size_t)s0 * 8);

    // preload edge ids + srcs for first 64 edges
    int e0 = 0, e1 = 0, src0 = 0, src1 = 0;
    if (lane < deg) e0 = g_elist[s0 + lane];
    if (lane + 32 < deg) e1 = g_elist[s0 + 32 + lane];
    if (lane < deg) src0 = ei[e0];
    if (lane + 32 < deg) src1 = ei[e1];

    float mymax = -FLT_MAX;
    {
        // per-lane tk slice: head h, terms t = p*40 .. p*40+39
        float tk[40];
#pragma unroll
        for (int tt = 0; tt < 40; tt++) {
            int t = p * 40 + tt;
            if (t < 64)
                tk[tt] = g_S[(size_t)n * 1088 + h * 64 + t];
            else {
                int j = t - 64;
                tk[tt] = g_V[(j % 3) * VPLANE + (size_t)n * 576 + h * 32 + (j / 3)];
            }
        }
        for (int i = 0; i < deg; i++) {
            int e, src;
            if (i < 64) {
                e   = __shfl_sync(F, (i < 32) ? e0 : e1, i & 31);
                src = __shfl_sync(F, (i < 32) ? src0 : src1, i & 31);
            } else {
                int ee = 0, ss = 0;
                if (lane == 0) { ee = g_elist[s0 + i]; ss = ei[ee]; }
                e = __shfl_sync(F, ee, 0);
                src = __shfl_sync(F, ss, 0);
            }
            const float4* xs = (const float4*)(x + (size_t)src * 160);
            ((float4*)s_x[wid])[lane] = xs[lane];
            if (lane < 8) ((float4*)s_x[wid])[32 + lane] = xs[32 + lane];
            __syncwarp();
            const float* xr = s_x[wid] + p * 40;
            float a = 0.f;
#pragma unroll
            for (int tt = 0; tt < 40; tt++) a += tk[tt] * xr[tt];
            a += __shfl_xor_sync(F, a, 1);
            a += __shfl_xor_sync(F, a, 2);
            if (p == 0) {
                a += g_QKself[src * 8 + h];
                lg[i * 8 + h] = a;
                mymax = fmaxf(mymax, a);
            }
            __syncwarp();
        }
    }

    // softmax (lanes p==0 own head h)
    if (p == 0 && deg > 0) {
        float den = 0.f;
        for (int i = 0; i < deg; i++) {
            float ex = expf(lg[i * 8 + h] - mymax);
            lg[i * 8 + h] = ex;
            den += ex;
        }
        float inv = 1.f / den;
        for (int i = 0; i < deg; i++) lg[i * 8 + h] *= inv;
    }
    __syncwarp();

    // aggregation: lane owns elems t*32 + lane, t = 0..39
    float acc[40];
#pragma unroll
    for (int tt = 0; tt < 40; tt++) acc[tt] = 0.f;

    for (int i = 0; i < deg; i++) {
        int e;
        if (i < 64) e = __shfl_sync(F, (i < 32) ? e0 : e1, i & 31);
        else {
            int ee = 0;
            if (lane == 0) ee = g_elist[s0 + i];
            e = __shfl_sync(F, ee, 0);
        }
        const float* fr = g_feat + (size_t)e * 160;
        float f0  = fr[lane];
        float f1  = fr[32 + lane];
        float fv0 = fr[64 + lane];
        float fv1 = fr[96 + lane];
        float fv2 = fr[128 + lane];
        float at[8];
#pragma unroll
        for (int hh = 0; hh < 8; hh++) at[hh] = lg[i * 8 + hh];
#pragma unroll
        for (int tt = 0; tt < 40; tt++) {
            int hT = (tt < 16) ? (tt >> 1) : ((tt - 16) & 7);
            float fval;
            if (tt < 16) fval = (tt & 1) ? f1 : f0;
            else {
                int c = (tt - 16) >> 3;
                fval = (c == 0) ? fv0 : ((c == 1) ? fv1 : fv2);
            }
            acc[tt] += at[hT] * fval;
        }
    }
#pragma unroll
    for (int tt = 0; tt < 40; tt++)
        g_agg[(size_t)n * 1280 + tt * 32 + lane] = acc[tt];
}

// ---------------- NormGate + output --------------------------------------------------
__global__ void __launch_bounds__(256) k_normgate(const float* __restrict__ ln_g,
                                                  const float* __restrict__ ln_b,
                                                  const float* __restrict__ W1,
                                                  const float* __restrict__ b1,
                                                  const float* __restrict__ W2,
                                                  const float* __restrict__ b2,
                                                  float* __restrict__ out) {
    __shared__ float sW1[96 * 96];
    __shared__ float sX[8][96];
    __shared__ float sH[8][96];
    int tid = threadIdx.x;
    int w = tid >> 5, lane = tid & 31;
    for (int i = tid; i < 9216; i += 256) sW1[i] = W1[i];
    __syncthreads();

    for (int sub = 0; sub < 4; sub++) {
        int n = blockIdx.x * 32 + w * 4 + sub;
        const float* mrow = g_m + (size_t)n * 160;
        float ms0 = mrow[lane], ms1 = mrow[32 + lane];
        float v0 = mrow[64 + lane * 3 + 0];
        float v1 = mrow[64 + lane * 3 + 1];
        float v2 = mrow[64 + lane * 3 + 2];
        float n00 = fabsf(ms0), n01 = fabsf(ms1);
        float n02 = sqrtf(v0 * v0 + v1 * v1 + v2 * v2);
        float s = n00 + n01 + n02;
        float s2 = n00 * n00 + n01 * n01 + n02 * n02;
#pragma unroll
        for (int o = 16; o; o >>= 1) {
            s  += __shfl_xor_sync(0xffffffffu, s, o);
            s2 += __shfl_xor_sync(0xffffffffu, s2, o);
        }
        float mu = s * (1.f / 96.f);
        float var = s2 * (1.f / 96.f) - mu * mu;
        float rstd = rsqrtf(var + 1e-5f);
        sX[w][lane]      = (n00 - mu) * rstd * ln_g[lane]      + ln_b[lane];
        sX[w][lane + 32] = (n01 - mu) * rstd * ln_g[lane + 32] + ln_b[lane + 32];
        sX[w][lane + 64] = (n02 - mu) * rstd * ln_g[lane + 64] + ln_b[lane + 64];
        __syncwarp();
#pragma unroll
        for (int t = 0; t < 3; t++) {
            int jp = lane + t * 32;
            float hs = b1[jp];
            for (int j = 0; j < 96; j++) hs += sX[w][j] * sW1[j * 96 + jp];
            sH[w][jp] = hs / (1.f + expf(-hs));
        }
        __syncwarp();
        float n0arr[3] = {n00, n01, n02};
        float f[3];
#pragma unroll
        for (int t = 0; t < 3; t++) {
            int jp = lane + t * 32;
            float gs = b2[jp];
            for (int j = 0; j < 96; j++) gs += sH[w][j] * W2[j * 96 + jp];
            float gg = gs / (1.f + expf(-gs));
            f[t] = gg / (n0arr[t] + 1e-6f);
        }
        out[n * 160 + lane]      = ms0 * f[0];
        out[n * 160 + 32 + lane] = ms1 * f[1];
        out[n * 160 + 64 + lane * 3 + 0] = v0 * f[2];
        out[n * 160 + 64 + lane * 3 + 1] = v1 * f[2];
        out[n * 160 + 64 + lane * 3 + 2] = v2 * f[2];
        __syncwarp();
    }
}

// ---------------- launch ----------------------------------------------------------------
extern "C" void kernel_launch(void* const* d_in, const int* in_sizes, int n_in,
                              void* d_out, int out_size) {
    const float* pseduo_x = (const float*)d_in[0];
    const float* rbf   = (const float*)d_in[1];
    const float* rsh   = (const float*)d_in[2];
    const int*   ei    = (const int*)d_in[3];
    const float* Wq_s  = (const float*)d_in[4];
    const float* Wq_v  = (const float*)d_in[5];
    const float* Wk_s  = (const float*)d_in[6];
    const float* Wk_v  = (const float*)d_in[7];
    const float* Wp_s  = (const float*)d_in[8];
    const float* Wp_v  = (const float*)d_in[9];
    const float* Wrbf  = (const float*)d_in[10];
    const float* Wv_s  = (const float*)d_in[11];
    const float* Wv_v  = (const float*)d_in[12];
    const float* Wm_s  = (const float*)d_in[13];
    const float* Wm_v  = (const float*)d_in[14];
    const float* ln_g  = (const float*)d_in[15];
    const float* ln_b  = (const float*)d_in[16];
    const float* W1    = (const float*)d_in[17];
    const float* b1    = (const float*)d_in[18];
    const float* W2    = (const float*)d_in[19];
    const float* b2    = (const float*)d_in[20];
    float* out = (float*)d_out;

    void* p;
    cudaGetSymbolAddress(&p, g_xT);  float* XT  = (float*)p;
    cudaGetSymbolAddress(&p, g_S);   float* S   = (float*)p;
    cudaGetSymbolAddress(&p, g_V);   float* V   = (float*)p;
    cudaGetSymbolAddress(&p, g_agg); float* AGG = (float*)p;
    cudaGetSymbolAddress(&p, g_m);   float* M   = (float*)p;
    cudaGetSymbolAddress(&p, g_Wts); float* Wts = (float*)p;
    cudaGetSymbolAddress(&p, g_Wtv); float* Wtv = (float*)p;
    cudaGetSymbolAddress(&p, g_Wcs); float* Wcs = (float*)p;
    cudaGetSymbolAddress(&p, g_Wcv); float* Wcv = (float*)p;

    k_pack2<<<50, 256>>>(Wq_s, Wq_v, Wk_s, Wk_v, Wp_s, Wp_v, Wv_s, Wv_v, Wm_s, Wm_v);
    k_xT<<<dim3(256, 5), dim3(32, 8)>>>(pseduo_x, XT);

    k_gemmT<64><<<dim3(17, 64, 1), 256>>>(XT, 0, 1, Wts, 1088, S, 1088, 0);
    k_gemmT<32><<<dim3(9, 64, 3), 256>>>(XT, 64, 3, Wtv, 576, V, 576, VPLANE);
    k_qkself2<<<1024, 256>>>(pseduo_x);

    k_hist<<<256, 256>>>(ei);
    k_scan<<<1, 1024>>>();
    k_scatter<<<256, 256>>>(ei);

    k_edgeprep<<<8192, 256>>>(rbf, rsh, ei, Wrbf);
    k_attn_agg2<<<1024, 256>>>(pseduo_x, ei);

    k_gemm<<<dim3(1, 128, 1), 256>>>(AGG, 1280, 1, 0, Wcs, 64,
                                     M, 160, 1, 0, 0, 512, 64);
    k_gemm<<<dim3(1, 128, 3), 256>>>(AGG + 512, 1280, 1, 256, Wcv, 32,
                                     M, 160, 3, 1, 64, 256, 32);

    k_normgate<<<256, 256>>>(ln_g, ln_b, W1, b1, W2, b2, out);
}